// round 11
// baseline (speedup 1.0000x reference)
#include <cuda_runtime.h>
#include <cuda_bf16.h>
#include <cstdint>

#define BB 8
#define HH 256
#define WW 256
#define HW 65536

// ==================== warp-MMA + cp.async helpers (base PTX) ====================
__device__ __forceinline__ uint32_t smem_u32(const void* p) {
    uint32_t a;
    asm("{ .reg .u64 t; cvta.to.shared.u64 t, %1; cvt.u32.u64 %0, t; }" : "=r"(a) : "l"(p));
    return a;
}
#define LDM4(r, addr)                                                              \
    asm volatile("ldmatrix.sync.aligned.m8n8.x4.shared.b16 {%0,%1,%2,%3}, [%4];"   \
        : "=r"((r)[0]), "=r"((r)[1]), "=r"((r)[2]), "=r"((r)[3]) : "r"(addr))
#define MMA(d, a, b0v, b1v)                                                        \
    asm volatile("mma.sync.aligned.m16n8k16.row.col.f32.bf16.bf16.f32 "            \
        "{%0,%1,%2,%3}, {%4,%5,%6,%7}, {%8,%9}, {%0,%1,%2,%3};"                    \
        : "+f"((d)[0]), "+f"((d)[1]), "+f"((d)[2]), "+f"((d)[3])                   \
        : "r"((a)[0]), "r"((a)[1]), "r"((a)[2]), "r"((a)[3]), "r"(b0v), "r"(b1v))
#define CP16(dst, src, n)                                                          \
    asm volatile("cp.async.cg.shared.global [%0], [%1], 16, %2;"                   \
        :: "r"(dst), "l"(src), "r"(n))
#define CP_COMMIT() asm volatile("cp.async.commit_group;")
#define CP_WAIT1()  asm volatile("cp.async.wait_group 1;")
#define CP_WAIT0()  asm volatile("cp.async.wait_group 0;")

// ==================== scratch ====================
__device__ __align__(128) float g_feat[(size_t)BB * 64 * HW];
__device__ __align__(128) float g_dx  [(size_t)BB * 64 * HW];
__device__ __align__(128) float g_gb  [(size_t)BB * 128 * HW];            // gamma 0-63, beta 64-127
__device__ __align__(128) __nv_bfloat16 g_in_h[(size_t)BB * HW * 64];
__device__ __align__(128) __nv_bfloat16 g_in_l[(size_t)BB * HW * 64];
__device__ __align__(128) __nv_bfloat16 g_actv_h[(size_t)BB * HW * 128];
__device__ __align__(128) __nv_bfloat16 g_actv_l[(size_t)BB * HW * 128];
__device__ __align__(128) float g_table[BB * 9 * 35 * 128];
__device__ __align__(128) float g_codes[BB * 35 * 64];
__device__ __align__(128) float g_sums [BB * 64 * 36];
__device__ __align__(128) float g_cnt  [BB * 36];
__device__ __align__(128) float g_stats[2 * BB * 64];
__device__ __align__(128) __nv_bfloat16 g_w1m[9 * 2 * 128 * 64];          // [tap][prec][oc'][ic]
__device__ __align__(128) __nv_bfloat16 g_w2m[9 * 2 * 2 * 128 * 64];      // [tap][kc][prec][oc'][ic]

// ==================== small kernels ====================
__global__ void k_zero() {
    int i = blockIdx.x * 256 + threadIdx.x;
    if (i < BB * 64 * 36) g_sums[i] = 0.f;
    if (i < BB * 36)      g_cnt[i]  = 0.f;
}

__global__ void k_wpack(const float* __restrict__ wc, const float* __restrict__ wc0,
                        const float* __restrict__ wg, const float* __restrict__ wb) {
    int i = blockIdx.x * 256 + threadIdx.x;
    if (i < 9 * 2 * 128 * 64) {
        int ic   = i & 63;
        int oc   = (i >> 6) & 127;
        int prec = (i >> 13) & 1;
        int tap  = i >> 14;
        const float* src = (oc < 64) ? wc : wc0;
        float wv = src[((oc & 63) * 64 + ic) * 9 + tap];
        __nv_bfloat16 hi = __float2bfloat16(wv);
        g_w1m[i] = prec ? __float2bfloat16(wv - __bfloat162float(hi)) : hi;
    }
    if (i < 9 * 2 * 2 * 128 * 64) {
        int ic   = i & 63;
        int ocp  = (i >> 6) & 127;
        int prec = (i >> 13) & 1;
        int kc   = (i >> 14) & 1;
        int tap  = i >> 15;
        const float* src = (ocp < 64) ? wg : wb;
        float wv = src[((ocp & 63) * 128 + kc * 64 + ic) * 9 + tap];
        __nv_bfloat16 hi = __float2bfloat16(wv);
        g_w2m[i] = prec ? __float2bfloat16(wv - __bfloat162float(hi)) : hi;
    }
}

// NCHW fp32 -> NHWC bf16 hi/lo split
__global__ void k_split(const float* __restrict__ in) {
    __shared__ float t[64][65];
    int b = blockIdx.y;
    int p0 = blockIdx.x * 64;
    int tid = threadIdx.x;
    for (int i = tid; i < 64 * 64; i += 256) {
        int c = i >> 6, px = i & 63;
        t[c][px] = in[((size_t)(b * 64 + c)) * HW + p0 + px];
    }
    __syncthreads();
    for (int i = tid; i < 64 * 64; i += 256) {
        int px = i >> 6, c = i & 63;
        float v = t[c][px];
        __nv_bfloat16 hi = __float2bfloat16(v);
        __nv_bfloat16 lo = __float2bfloat16(v - __bfloat162float(hi));
        size_t o = (((size_t)b * HW + p0 + px) << 6) + c;
        g_in_h[o] = hi;
        g_in_l[o] = lo;
    }
}

// ==================== MMA smem constants ====================
static constexpr int AROW    = 132 * 144;              // 19008 per input row
static constexpr int A_PREC  = 4 * AROW;               // 76032 per precision (4 rows)
static constexpr int SW_OFF  = 2 * A_PREC;             // 152064
static constexpr int SW_PREC = 128 * 144;              // 18432
static constexpr int WBUF    = 2 * SW_PREC;            // 36864 per W buffer
static constexpr int SMEM_MMA = SW_OFF + 2 * WBUF;     // 225792

// ==================== conv1+conv_c0: A-resident, W cp.async double-buffered ====================
// CTA: 2 rows x 128px x 128oc'. 8 warps 64x64. grid (2, 128, 8).
__global__ void __launch_bounds__(256, 1)
k_conv1mma(const float* __restrict__ bc_, const float* __restrict__ bc0_) {
    extern __shared__ __align__(1024) char sm[];
    uint32_t sa = smem_u32(sm);
    int tid = threadIdx.x;
    int w = tid >> 5, l = tid & 31;
    int x0 = blockIdx.x * 128, y0 = blockIdx.y * 2, b = blockIdx.z;
    int mwarp = w & 3, nwarp = w >> 2;
    int r = mwarp >> 1, px0 = (mwarp & 1) * 64;
    int ncol = nwarp * 64;

    // stage A window: 2 prec x 4 input rows x 130 px x 8 chunks
    for (int idx = tid; idx < 8320; idx += 256) {
        int prec = idx / 4160; int e = idx % 4160;
        int irow = e / 1040;   int e2 = e % 1040;
        int jj = e2 >> 3, ch = e2 & 7;
        int iy = y0 - 1 + irow, x = x0 - 1 + jj;
        bool ok = ((unsigned)iy < 256u) && ((unsigned)x < 256u);
        int iyc = ok ? iy : 0, xc = ok ? x : 0;
        const __nv_bfloat16* src = prec ? g_in_l : g_in_h;
        const void* gp = src + (((size_t)b * HW + iyc * 256 + xc) << 6) + ch * 8;
        CP16(sa + prec * A_PREC + irow * AROW + jj * 144 + ch * 16, gp, ok ? 16 : 0);
    }
    CP_COMMIT();
    // stage W(0) into buf 0
    {
        const char* wg = (const char*)g_w1m;
        for (int idx = tid; idx < 2048; idx += 256) {
            int prec = idx >> 10, e = idx & 1023, oc = e >> 3, ch = e & 7;
            CP16(sa + SW_OFF + prec * SW_PREC + oc * 144 + ch * 16, wg + idx * 16, 16);
        }
        CP_COMMIT();
    }

    float acc[4][8][4];
#pragma unroll
    for (int mt = 0; mt < 4; mt++)
#pragma unroll
        for (int nt = 0; nt < 8; nt++)
#pragma unroll
            for (int e = 0; e < 4; e++) acc[mt][nt][e] = 0.f;

    for (int t = 0; t < 9; t++) {
        int dy = t / 3, dxk = t % 3, buf = t & 1;
        if (t > 0) __syncthreads();
        if (t < 8) {
            const char* wg = (const char*)g_w1m + (size_t)(t + 1) * 32768;
            int wb_ = (t + 1) & 1;
            for (int idx = tid; idx < 2048; idx += 256) {
                int prec = idx >> 10, e = idx & 1023, oc = e >> 3, ch = e & 7;
                CP16(sa + SW_OFF + wb_ * WBUF + prec * SW_PREC + oc * 144 + ch * 16,
                     wg + idx * 16, 16);
            }
            CP_COMMIT();
            CP_WAIT1();
        } else {
            CP_WAIT0();
        }
        __syncthreads();

        uint32_t aBase = sa + (r + dy) * AROW + (px0 + dxk + (l & 15)) * 144 + (l >> 4) * 16;
        uint32_t bBase = sa + SW_OFF + buf * WBUF +
                         (ncol + ((l >> 4) << 3) + (l & 7)) * 144 + ((l >> 3) & 1) * 16;
#pragma unroll
        for (int ks = 0; ks < 4; ks++) {
            uint32_t ah[4][4], al[4][4];
#pragma unroll
            for (int mt = 0; mt < 4; mt++) {
                LDM4(ah[mt], aBase + mt * 16 * 144 + ks * 32);
                LDM4(al[mt], aBase + A_PREC + mt * 16 * 144 + ks * 32);
            }
#pragma unroll
            for (int np = 0; np < 4; np++) {
                uint32_t bh[4], bl[4];
                LDM4(bh, bBase + np * 16 * 144 + ks * 32);
                LDM4(bl, bBase + SW_PREC + np * 16 * 144 + ks * 32);
#pragma unroll
                for (int mt = 0; mt < 4; mt++) {
                    MMA(acc[mt][np * 2 + 0], ah[mt], bh[0], bh[1]);
                    MMA(acc[mt][np * 2 + 0], ah[mt], bl[0], bl[1]);
                    MMA(acc[mt][np * 2 + 0], al[mt], bh[0], bh[1]);
                    MMA(acc[mt][np * 2 + 1], ah[mt], bh[2], bh[3]);
                    MMA(acc[mt][np * 2 + 1], ah[mt], bl[2], bl[3]);
                    MMA(acc[mt][np * 2 + 1], al[mt], bh[2], bh[3]);
                }
            }
        }
    }

    // epilogue: nwarp 0 -> lrelu -> g_feat; nwarp 1 -> raw -> g_dx
    bool isFeat = (nwarp == 0);
    float* dst = isFeat ? g_feat : g_dx;
    const float* bias = isFeat ? bc_ : bc0_;
    int y = y0 + r;
    int g = l >> 2, tg = l & 3;
#pragma unroll
    for (int nt = 0; nt < 8; nt++) {
        int c0 = nt * 8 + tg * 2;
        float bias0 = bias[c0], bias1 = bias[c0 + 1];
#pragma unroll
        for (int mt = 0; mt < 4; mt++) {
            int px = x0 + px0 + mt * 16 + g;
            size_t o0 = ((size_t)(b * 64 + c0)) * HW + y * 256 + px;
            float v0 = acc[mt][nt][0] + bias0;
            float v1 = acc[mt][nt][1] + bias1;
            float v2 = acc[mt][nt][2] + bias0;
            float v3 = acc[mt][nt][3] + bias1;
            if (isFeat) {
                v0 = v0 >= 0.f ? v0 : 0.2f * v0;
                v1 = v1 >= 0.f ? v1 : 0.2f * v1;
                v2 = v2 >= 0.f ? v2 : 0.2f * v2;
                v3 = v3 >= 0.f ? v3 : 0.2f * v3;
            }
            dst[o0]          = v0;
            dst[o0 + HW]     = v1;
            dst[o0 + 8]      = v2;
            dst[o0 + HW + 8] = v3;
        }
    }
}

// ==================== conv2 (IC=128): A-resident per kc, W double-buffered ====================
__global__ void __launch_bounds__(256, 1)
k_conv2mma(const float* __restrict__ bg_, const float* __restrict__ bb_) {
    extern __shared__ __align__(1024) char sm[];
    uint32_t sa = smem_u32(sm);
    int tid = threadIdx.x;
    int w = tid >> 5, l = tid & 31;
    int x0 = blockIdx.x * 128, y0 = blockIdx.y * 2, b = blockIdx.z;
    int mwarp = w & 3, nwarp = w >> 2;
    int r = mwarp >> 1, px0 = (mwarp & 1) * 64;
    int ncol = nwarp * 64;

    auto stageA = [&](int kc) {
        for (int idx = tid; idx < 8320; idx += 256) {
            int prec = idx / 4160; int e = idx % 4160;
            int irow = e / 1040;   int e2 = e % 1040;
            int jj = e2 >> 3, ch = e2 & 7;
            int iy = y0 - 1 + irow, x = x0 - 1 + jj;
            bool ok = ((unsigned)iy < 256u) && ((unsigned)x < 256u);
            int iyc = ok ? iy : 0, xc = ok ? x : 0;
            const __nv_bfloat16* src = prec ? g_actv_l : g_actv_h;
            const void* gp = src + (((size_t)b * HW + iyc * 256 + xc) << 7) + kc * 64 + ch * 8;
            CP16(sa + prec * A_PREC + irow * AROW + jj * 144 + ch * 16, gp, ok ? 16 : 0);
        }
        CP_COMMIT();
    };
    auto stageW = [&](int t1, int buf) {
        int tap = t1 % 9, kc = t1 / 9;
        const char* wg = (const char*)g_w2m + (size_t)(tap * 2 + kc) * 32768;
        for (int idx = tid; idx < 2048; idx += 256) {
            int prec = idx >> 10, e = idx & 1023, oc = e >> 3, ch = e & 7;
            CP16(sa + SW_OFF + buf * WBUF + prec * SW_PREC + oc * 144 + ch * 16,
                 wg + idx * 16, 16);
        }
        CP_COMMIT();
    };

    float acc[4][8][4];
#pragma unroll
    for (int mt = 0; mt < 4; mt++)
#pragma unroll
        for (int nt = 0; nt < 8; nt++)
#pragma unroll
            for (int e = 0; e < 4; e++) acc[mt][nt][e] = 0.f;

    stageA(0);
    stageW(0, 0);

    for (int t = 0; t < 18; t++) {
        int kc = t / 9, tap = t % 9;
        int dy = tap / 3, dxk = tap % 3, buf = t & 1;
        if (t > 0) __syncthreads();
        if (t == 9) stageA(1);
        if (t < 17) {
            stageW(t + 1, (t + 1) & 1);
            CP_WAIT1();
        } else {
            CP_WAIT0();
        }
        __syncthreads();

        uint32_t aBase = sa + (r + dy) * AROW + (px0 + dxk + (l & 15)) * 144 + (l >> 4) * 16;
        uint32_t bBase = sa + SW_OFF + buf * WBUF +
                         (ncol + ((l >> 4) << 3) + (l & 7)) * 144 + ((l >> 3) & 1) * 16;
#pragma unroll
        for (int ks = 0; ks < 4; ks++) {
            uint32_t ah[4][4], al[4][4];
#pragma unroll
            for (int mt = 0; mt < 4; mt++) {
                LDM4(ah[mt], aBase + mt * 16 * 144 + ks * 32);
                LDM4(al[mt], aBase + A_PREC + mt * 16 * 144 + ks * 32);
            }
#pragma unroll
            for (int np = 0; np < 4; np++) {
                uint32_t bh[4], bl[4];
                LDM4(bh, bBase + np * 16 * 144 + ks * 32);
                LDM4(bl, bBase + SW_PREC + np * 16 * 144 + ks * 32);
#pragma unroll
                for (int mt = 0; mt < 4; mt++) {
                    MMA(acc[mt][np * 2 + 0], ah[mt], bh[0], bh[1]);
                    MMA(acc[mt][np * 2 + 0], ah[mt], bl[0], bl[1]);
                    MMA(acc[mt][np * 2 + 0], al[mt], bh[0], bh[1]);
                    MMA(acc[mt][np * 2 + 1], ah[mt], bh[2], bh[3]);
                    MMA(acc[mt][np * 2 + 1], ah[mt], bl[2], bl[3]);
                    MMA(acc[mt][np * 2 + 1], al[mt], bh[2], bh[3]);
                }
            }
        }
    }

    // epilogue: g_gb channels 0-63 gamma, 64-127 beta (+bias)
    int y = y0 + r;
    int g = l >> 2, tg = l & 3;
#pragma unroll
    for (int nt = 0; nt < 8; nt++) {
        int oc0 = ncol + nt * 8 + tg * 2;
        float bias0 = (oc0 < 64) ? bg_[oc0] : bb_[oc0 - 64];
        float bias1 = (oc0 + 1 < 64) ? bg_[oc0 + 1] : bb_[oc0 - 63];
#pragma unroll
        for (int mt = 0; mt < 4; mt++) {
            int px = x0 + px0 + mt * 16 + g;
            size_t o0 = ((size_t)(b * 128 + oc0)) * HW + y * 256 + px;
            g_gb[o0]          = acc[mt][nt][0] + bias0;
            g_gb[o0 + HW]     = acc[mt][nt][1] + bias1;
            g_gb[o0 + 8]      = acc[mt][nt][2] + bias0;
            g_gb[o0 + HW + 8] = acc[mt][nt][3] + bias1;
        }
    }
}

// ==================== instance-norm stats ====================
__global__ void k_stats() {
    int bc = blockIdx.x;
    int tid = threadIdx.x;
    const float4* p = (const float4*)(g_dx + (size_t)bc * HW);
    float s = 0.f, s2 = 0.f;
    for (int i = tid; i < HW / 4; i += 256) {
        float4 v = p[i];
        s  += v.x + v.y + v.z + v.w;
        s2 += v.x * v.x + v.y * v.y + v.z * v.z + v.w * v.w;
    }
    __shared__ float rs[256], rq[256];
    rs[tid] = s; rq[tid] = s2;
    __syncthreads();
    for (int o = 128; o > 0; o >>= 1) {
        if (tid < o) { rs[tid] += rs[tid + o]; rq[tid] += rq[tid + o]; }
        __syncthreads();
    }
    if (tid == 0) {
        float m = rs[0] * (1.f / HW);
        float var = rq[0] * (1.f / HW) - m * m;
        g_stats[bc] = m;
        g_stats[512 + bc] = rsqrtf(var + 1e-5f);
    }
}

// ==================== masked per-class mean pooling ====================
__global__ void k_pool(const int* __restrict__ seg, const float* __restrict__ bg,
                       const float* __restrict__ mask) {
    __shared__ float s_sum[64 * 36];
    __shared__ float s_cnt[36];
    int tid = threadIdx.x;
    for (int i = tid; i < 64 * 36; i += 256) s_sum[i] = 0.f;
    if (tid < 36) s_cnt[tid] = 0.f;
    __syncthreads();
    int b = blockIdx.y;
    int lane = tid & 31, cg = tid >> 5;
    int base = blockIdx.x * 4096;
    for (int p0 = 0; p0 < 4096; p0 += 32) {
        int p = base + p0 + lane;
        int s = seg[b * HW + p];
        bool q = (bg[b * HW + p] * (1.f - mask[b * HW + p])) > 0.f;
        if (q && cg == 0) atomicAdd(&s_cnt[s], 1.f);
        if (q) {
#pragma unroll
            for (int cc = 0; cc < 8; cc++) {
                int c = cg + cc * 8;
                float f = g_feat[((size_t)(b * 64 + c)) * HW + p];
                atomicAdd(&s_sum[c * 36 + s], f);
            }
        }
    }
    __syncthreads();
    for (int i = tid; i < 64 * 36; i += 256) {
        float v = s_sum[i];
        if (v != 0.f) atomicAdd(&g_sums[b * 2304 + i], v);
    }
    if (tid < 36 && s_cnt[tid] != 0.f) atomicAdd(&g_cnt[b * 36 + tid], s_cnt[tid]);
}

__global__ void k_codes() {
    int i = blockIdx.x * 256 + threadIdx.x;
    if (i >= BB * 35 * 64) return;
    int b = i / (35 * 64); int s = (i / 64) % 35; int f = i & 63;
    float cnt = g_cnt[b * 36 + s];
    bool keep = !(s >= 24 && s <= 33);
    float v = 0.f;
    if (cnt > 0.f && keep) v = g_sums[b * 2304 + f * 36 + s] / cnt;
    g_codes[i] = v;
}

__global__ void k_table(const float* __restrict__ w_sh) {
    int b = blockIdx.x / 9, k = blockIdx.x % 9;
    int o = threadIdx.x;  // 128
    __shared__ float swt[64][128];
    __shared__ float sc[64];
    for (int f = 0; f < 64; f++) swt[f][o] = w_sh[(o * 99 + f) * 9 + k];
    for (int s = 0; s < 35; s++) {
        __syncthreads();
        if (o < 64) sc[o] = g_codes[(b * 35 + s) * 64 + o];
        __syncthreads();
        float acc = w_sh[(o * 99 + 64 + s) * 9 + k];
#pragma unroll 8
        for (int f = 0; f < 64; f++)
            acc = fmaf(swt[f][o], sc[f], acc);
        g_table[((b * 9 + k) * 35 + s) * 128 + o] = acc;
    }
}

// ---------------- actv = relu(b_sh + table conv) -> NHWC bf16 hi/lo ----------------
__global__ void k_actv(const int* __restrict__ seg, const float* __restrict__ bg,
                       const float* __restrict__ bsh) {
    __shared__ int ns[324];
    int b = blockIdx.z;
    int x0 = blockIdx.x * 16, y0 = blockIdx.y * 16;
    int tid = threadIdx.x;
    for (int i = tid; i < 324; i += 256) {
        int r = i / 18, c = i % 18;
        int gy = y0 - 1 + r, gx = x0 - 1 + c;
        int v = -1;
        if ((unsigned)gy < 256u && (unsigned)gx < 256u) {
            int p = gy * 256 + gx;
            if (bg[b * HW + p] > 0.f) v = seg[b * HW + p];
        }
        ns[i] = v;
    }
    __syncthreads();
    int oq = tid & 31, pg = tid >> 5;
    const float4* T4 = (const float4*)g_table + (size_t)b * 9 * 35 * 32;
    float4 bias = ((const float4*)bsh)[oq];
    for (int pp = pg * 32; pp < pg * 32 + 32; pp++) {
        int ly = pp >> 4, lx = pp & 15;
        float4 a = bias;
#pragma unroll
        for (int ky = 0; ky < 3; ky++)
#pragma unroll
            for (int kx = 0; kx < 3; kx++) {
                int idx = ns[(ly + ky) * 18 + lx + kx];
                if (idx >= 0) {
                    float4 t = T4[((ky * 3 + kx) * 35 + idx) * 32 + oq];
                    a.x += t.x; a.y += t.y; a.z += t.z; a.w += t.w;
                }
            }
        a.x = fmaxf(a.x, 0.f); a.y = fmaxf(a.y, 0.f);
        a.z = fmaxf(a.z, 0.f); a.w = fmaxf(a.w, 0.f);
        __nv_bfloat16 h0 = __float2bfloat16(a.x), h1 = __float2bfloat16(a.y);
        __nv_bfloat16 h2 = __float2bfloat16(a.z), h3 = __float2bfloat16(a.w);
        __nv_bfloat16 l0 = __float2bfloat16(a.x - __bfloat162float(h0));
        __nv_bfloat16 l1 = __float2bfloat16(a.y - __bfloat162float(h1));
        __nv_bfloat16 l2 = __float2bfloat16(a.z - __bfloat162float(h2));
        __nv_bfloat16 l3 = __float2bfloat16(a.w - __bfloat162float(h3));
        int gp = (y0 + ly) * 256 + x0 + lx;
        size_t base = (((size_t)b * HW + gp) << 7) + oq * 4;
        uint2 hv, lv;
        hv.x = (uint32_t)__bfloat16_as_ushort(h0) | ((uint32_t)__bfloat16_as_ushort(h1) << 16);
        hv.y = (uint32_t)__bfloat16_as_ushort(h2) | ((uint32_t)__bfloat16_as_ushort(h3) << 16);
        lv.x = (uint32_t)__bfloat16_as_ushort(l0) | ((uint32_t)__bfloat16_as_ushort(l1) << 16);
        lv.y = (uint32_t)__bfloat16_as_ushort(l2) | ((uint32_t)__bfloat16_as_ushort(l3) << 16);
        *(uint2*)(g_actv_h + base) = hv;
        *(uint2*)(g_actv_l + base) = lv;
    }
}

// ---------------- final: lrelu(instnorm(dx)*(1+gamma)+beta) ----------------
__global__ void k_final(float* __restrict__ out) {
    size_t gi = (size_t)blockIdx.x * 256 + threadIdx.x;
    size_t e = gi * 4;
    int b = (int)(e / ((size_t)64 * HW));
    int c = (int)((e / HW) & 63);
    size_t p = e % HW;
    float4 dx = ((const float4*)g_dx)[gi];
    float4 ga = ((const float4*)g_gb)[((size_t)(b * 128 + c) * HW + p) / 4];
    float4 be = ((const float4*)g_gb)[((size_t)(b * 128 + 64 + c) * HW + p) / 4];
    float m = g_stats[b * 64 + c], r = g_stats[512 + b * 64 + c];
    float4 o;
    float v;
    v = (dx.x - m) * r * (1.f + ga.x) + be.x; o.x = v >= 0.f ? v : 0.2f * v;
    v = (dx.y - m) * r * (1.f + ga.y) + be.y; o.y = v >= 0.f ? v : 0.2f * v;
    v = (dx.z - m) * r * (1.f + ga.z) + be.z; o.z = v >= 0.f ? v : 0.2f * v;
    v = (dx.w - m) * r * (1.f + ga.w) + be.w; o.w = v >= 0.f ? v : 0.2f * v;
    ((float4*)out)[gi] = o;
}

// ==================== host ====================
extern "C" void kernel_launch(void* const* d_in, const int* in_sizes, int n_in,
                              void* d_out, int out_size) {
    const float* featmap_in = (const float*)d_in[0];
    const int*   seg        = (const int*)  d_in[1];
    const float* bg         = (const float*)d_in[2];
    const float* mask       = (const float*)d_in[3];
    const float* w_conv     = (const float*)d_in[4];
    const float* b_conv     = (const float*)d_in[5];
    const float* w_c0       = (const float*)d_in[6];
    const float* b_c0       = (const float*)d_in[7];
    const float* w_sh       = (const float*)d_in[8];
    const float* b_sh       = (const float*)d_in[9];
    const float* w_g        = (const float*)d_in[10];
    const float* b_g        = (const float*)d_in[11];
    const float* w_b        = (const float*)d_in[12];
    const float* b_b        = (const float*)d_in[13];

    cudaFuncSetAttribute(k_conv1mma, cudaFuncAttributeMaxDynamicSharedMemorySize, SMEM_MMA);
    cudaFuncSetAttribute(k_conv2mma, cudaFuncAttributeMaxDynamicSharedMemorySize, SMEM_MMA);

    k_zero<<<72, 256>>>();
    k_wpack<<<1152, 256>>>(w_conv, w_c0, w_g, w_b);
    k_split<<<dim3(1024, 8), 256>>>(featmap_in);

    // conv1 (lrelu -> g_feat) + conv_c0 (raw -> g_dx)
    k_conv1mma<<<dim3(2, 128, 8), 256, SMEM_MMA>>>(b_conv, b_c0);

    k_stats<<<512, 256>>>();
    k_pool<<<dim3(16, 8), 256>>>(seg, bg, mask);
    k_codes<<<70, 256>>>();
    k_table<<<72, 128>>>(w_sh);
    k_actv<<<dim3(16, 16, 8), 256>>>(seg, bg, b_sh);

    // gamma/beta conv -> g_gb
    k_conv2mma<<<dim3(2, 128, 8), 256, SMEM_MMA>>>(b_g, b_b);

    k_final<<<32768, 256>>>((float*)d_out);
}

// round 12
// speedup vs baseline: 1.0537x; 1.0537x over previous
#include <cuda_runtime.h>
#include <cuda_bf16.h>
#include <cstdint>

#define BB 8
#define HH 256
#define WW 256
#define HW 65536

// ==================== warp-MMA + cp.async helpers (base PTX) ====================
__device__ __forceinline__ uint32_t smem_u32(const void* p) {
    uint32_t a;
    asm("{ .reg .u64 t; cvta.to.shared.u64 t, %1; cvt.u32.u64 %0, t; }" : "=r"(a) : "l"(p));
    return a;
}
#define LDM4(r, addr)                                                              \
    asm volatile("ldmatrix.sync.aligned.m8n8.x4.shared.b16 {%0,%1,%2,%3}, [%4];"   \
        : "=r"((r)[0]), "=r"((r)[1]), "=r"((r)[2]), "=r"((r)[3]) : "r"(addr))
#define MMA(d, a, b0v, b1v)                                                        \
    asm volatile("mma.sync.aligned.m16n8k16.row.col.f32.bf16.bf16.f32 "            \
        "{%0,%1,%2,%3}, {%4,%5,%6,%7}, {%8,%9}, {%0,%1,%2,%3};"                    \
        : "+f"((d)[0]), "+f"((d)[1]), "+f"((d)[2]), "+f"((d)[3])                   \
        : "r"((a)[0]), "r"((a)[1]), "r"((a)[2]), "r"((a)[3]), "r"(b0v), "r"(b1v))
#define CP16(dst, src, n)                                                          \
    asm volatile("cp.async.cg.shared.global [%0], [%1], 16, %2;"                   \
        :: "r"(dst), "l"(src), "r"(n))
#define CP_COMMIT() asm volatile("cp.async.commit_group;")
#define CP_WAIT1()  asm volatile("cp.async.wait_group 1;")
#define CP_WAIT0()  asm volatile("cp.async.wait_group 0;")

// ==================== scratch ====================
__device__ __align__(128) float g_feat[(size_t)BB * 64 * HW];
__device__ __align__(128) float g_dx  [(size_t)BB * 64 * HW];
__device__ __align__(128) __nv_bfloat16 g_in_h[(size_t)BB * HW * 64];
__device__ __align__(128) __nv_bfloat16 g_in_l[(size_t)BB * HW * 64];
__device__ __align__(128) __nv_bfloat16 g_actv_h[(size_t)BB * HW * 128];
__device__ __align__(128) __nv_bfloat16 g_actv_l[(size_t)BB * HW * 128];
__device__ __align__(128) float g_table[BB * 9 * 35 * 128];
__device__ __align__(128) float g_codes[BB * 35 * 64];
__device__ __align__(128) float g_sums [BB * 64 * 36];
__device__ __align__(128) float g_cnt  [BB * 36];
__device__ __align__(128) float g_stats[2 * BB * 64];
__device__ __align__(128) __nv_bfloat16 g_w1m[9 * 2 * 128 * 64];          // [tap][prec][oc'][ic]
__device__ __align__(128) __nv_bfloat16 g_w2m[9 * 2 * 2 * 128 * 64];      // [tap][kc][prec][oc'][ic]

// ==================== small kernels ====================
__global__ void k_zero() {
    int i = blockIdx.x * 256 + threadIdx.x;
    if (i < BB * 64 * 36) g_sums[i] = 0.f;
    if (i < BB * 36)      g_cnt[i]  = 0.f;
}

__global__ void k_wpack(const float* __restrict__ wc, const float* __restrict__ wc0,
                        const float* __restrict__ wg, const float* __restrict__ wb) {
    int i = blockIdx.x * 256 + threadIdx.x;
    if (i < 9 * 2 * 128 * 64) {
        int ic   = i & 63;
        int oc   = (i >> 6) & 127;
        int prec = (i >> 13) & 1;
        int tap  = i >> 14;
        const float* src = (oc < 64) ? wc : wc0;
        float wv = src[((oc & 63) * 64 + ic) * 9 + tap];
        __nv_bfloat16 hi = __float2bfloat16(wv);
        g_w1m[i] = prec ? __float2bfloat16(wv - __bfloat162float(hi)) : hi;
    }
    if (i < 9 * 2 * 2 * 128 * 64) {
        int ic   = i & 63;
        int ocp  = (i >> 6) & 127;
        int prec = (i >> 13) & 1;
        int kc   = (i >> 14) & 1;
        int tap  = i >> 15;
        const float* src = (ocp < 64) ? wg : wb;
        float wv = src[((ocp & 63) * 128 + kc * 64 + ic) * 9 + tap];
        __nv_bfloat16 hi = __float2bfloat16(wv);
        g_w2m[i] = prec ? __float2bfloat16(wv - __bfloat162float(hi)) : hi;
    }
}

// NCHW fp32 -> NHWC bf16 hi/lo split (vectorized 8B stores)
__global__ void k_split(const float* __restrict__ in) {
    __shared__ float t[64][65];
    int b = blockIdx.y;
    int p0 = blockIdx.x * 64;
    int tid = threadIdx.x;
    for (int i = tid; i < 64 * 64; i += 256) {
        int c = i >> 6, px = i & 63;
        t[c][px] = in[((size_t)(b * 64 + c)) * HW + p0 + px];
    }
    __syncthreads();
    for (int i = tid; i < 1024; i += 256) {
        int px = i >> 4, c4 = (i & 15) * 4;
        uint32_t h01, h23, l01, l23;
        {
            float v0 = t[c4 + 0][px], v1 = t[c4 + 1][px];
            float v2 = t[c4 + 2][px], v3 = t[c4 + 3][px];
            __nv_bfloat16 h0 = __float2bfloat16(v0), h1 = __float2bfloat16(v1);
            __nv_bfloat16 h2 = __float2bfloat16(v2), h3 = __float2bfloat16(v3);
            __nv_bfloat16 l0 = __float2bfloat16(v0 - __bfloat162float(h0));
            __nv_bfloat16 l1 = __float2bfloat16(v1 - __bfloat162float(h1));
            __nv_bfloat16 l2 = __float2bfloat16(v2 - __bfloat162float(h2));
            __nv_bfloat16 l3 = __float2bfloat16(v3 - __bfloat162float(h3));
            h01 = (uint32_t)__bfloat16_as_ushort(h0) | ((uint32_t)__bfloat16_as_ushort(h1) << 16);
            h23 = (uint32_t)__bfloat16_as_ushort(h2) | ((uint32_t)__bfloat16_as_ushort(h3) << 16);
            l01 = (uint32_t)__bfloat16_as_ushort(l0) | ((uint32_t)__bfloat16_as_ushort(l1) << 16);
            l23 = (uint32_t)__bfloat16_as_ushort(l2) | ((uint32_t)__bfloat16_as_ushort(l3) << 16);
        }
        size_t o = (((size_t)b * HW + p0 + px) << 6) + c4;
        *(uint2*)(g_in_h + o) = make_uint2(h01, h23);
        *(uint2*)(g_in_l + o) = make_uint2(l01, l23);
    }
}

// ==================== MMA smem constants (R10 layout) ====================
static constexpr int SA_PREC = 132 * 144;              // 19008
static constexpr int SW_OFF  = 2 * SA_PREC;            // 38016
static constexpr int SW_PREC = 128 * 144;              // 18432
static constexpr int WBUF    = 2 * SW_PREC;            // 36864 per W buffer
static constexpr int SMEM_MMA = SW_OFF + 2 * WBUF;     // 111744

// ==================== conv1+conv_c0: warp-MMA bf16x3, cp.async pipelined (R10) ====================
__global__ void __launch_bounds__(128, 2)
k_conv1mma(const float* __restrict__ bc_, const float* __restrict__ bc0_) {
    extern __shared__ __align__(1024) char sm[];
    uint32_t sa = smem_u32(sm);
    int tid = threadIdx.x;
    int w = tid >> 5, l = tid & 31;
    int x0 = blockIdx.x * 128, y = blockIdx.y, b = blockIdx.z;
    int mrow = (w & 1) * 64, ncol = (w >> 1) * 64;

    auto stageW = [&](int tap, int buf) {
        const char* wg = (const char*)g_w1m + (size_t)tap * 32768;
        for (int idx = tid; idx < 2048; idx += 128) {
            int prec = idx >> 10, e = idx & 1023, oc = e >> 3, ch = e & 7;
            uint32_t d = sa + SW_OFF + buf * WBUF + prec * SW_PREC + oc * 144 + ch * 16;
            CP16(d, wg + idx * 16, 16);
        }
        CP_COMMIT();
    };
    auto stageA = [&](int dy) {
        int iy = y + dy - 1;
        bool rowok = ((unsigned)iy < 256u);
        int iyc = rowok ? iy : 0;
        for (int idx = tid; idx < 2080; idx += 128) {
            int prec = idx >= 1040; int e = idx - (prec ? 1040 : 0);
            int j = e >> 3, ch = e & 7;
            int x = x0 - 1 + j;
            bool ok = rowok && ((unsigned)x < 256u);
            int xc = ok ? x : 0;
            const __nv_bfloat16* src = prec ? g_in_l : g_in_h;
            const void* gp = src + (((size_t)b * HW + iyc * 256 + xc) << 6) + ch * 8;
            CP16(sa + prec * SA_PREC + j * 144 + ch * 16, gp, ok ? 16 : 0);
        }
        CP_COMMIT();
    };

    float acc[4][8][4];
#pragma unroll
    for (int mt = 0; mt < 4; mt++)
#pragma unroll
        for (int nt = 0; nt < 8; nt++)
#pragma unroll
            for (int e = 0; e < 4; e++) acc[mt][nt][e] = 0.f;

    stageW(0, 0);
    for (int t = 0; t < 9; t++) {
        int dy = t / 3, dxk = t % 3, buf = t & 1;
        __syncthreads();
        if (dxk == 0) stageA(dy);
        if (t < 8) stageW(t + 1, (t + 1) & 1);
        if (t < 8) { CP_WAIT1(); } else { CP_WAIT0(); }
        __syncthreads();

        uint32_t aBase = sa + (mrow + dxk + (l & 15)) * 144 + (l >> 4) * 16;
        uint32_t bBase = sa + SW_OFF + buf * WBUF +
                         (ncol + ((l >> 4) << 3) + (l & 7)) * 144 + ((l >> 3) & 1) * 16;
#pragma unroll
        for (int ks = 0; ks < 4; ks++) {
            uint32_t ah[4][4], al[4][4];
#pragma unroll
            for (int mt = 0; mt < 4; mt++) {
                LDM4(ah[mt], aBase + mt * 16 * 144 + ks * 32);
                LDM4(al[mt], aBase + SA_PREC + mt * 16 * 144 + ks * 32);
            }
#pragma unroll
            for (int np = 0; np < 4; np++) {
                uint32_t bh[4], bl[4];
                LDM4(bh, bBase + np * 16 * 144 + ks * 32);
                LDM4(bl, bBase + SW_PREC + np * 16 * 144 + ks * 32);
#pragma unroll
                for (int mt = 0; mt < 4; mt++) {
                    MMA(acc[mt][np * 2 + 0], ah[mt], bh[0], bh[1]);
                    MMA(acc[mt][np * 2 + 0], ah[mt], bl[0], bl[1]);
                    MMA(acc[mt][np * 2 + 0], al[mt], bh[0], bh[1]);
                    MMA(acc[mt][np * 2 + 1], ah[mt], bh[2], bh[3]);
                    MMA(acc[mt][np * 2 + 1], ah[mt], bl[2], bl[3]);
                    MMA(acc[mt][np * 2 + 1], al[mt], bh[2], bh[3]);
                }
            }
        }
    }

    bool isFeat = (ncol == 0);
    float* dst = isFeat ? g_feat : g_dx;
    const float* bias = isFeat ? bc_ : bc0_;
    int g = l >> 2, tg = l & 3;
#pragma unroll
    for (int nt = 0; nt < 8; nt++) {
        int c0 = (ncol & 63) + nt * 8 + tg * 2;
        float bias0 = bias[c0], bias1 = bias[c0 + 1];
#pragma unroll
        for (int mt = 0; mt < 4; mt++) {
            int px = x0 + mrow + mt * 16 + g;
            size_t o0 = ((size_t)(b * 64 + c0)) * HW + y * 256 + px;
            float v0 = acc[mt][nt][0] + bias0;
            float v1 = acc[mt][nt][1] + bias1;
            float v2 = acc[mt][nt][2] + bias0;
            float v3 = acc[mt][nt][3] + bias1;
            if (isFeat) {
                v0 = v0 >= 0.f ? v0 : 0.2f * v0;
                v1 = v1 >= 0.f ? v1 : 0.2f * v1;
                v2 = v2 >= 0.f ? v2 : 0.2f * v2;
                v3 = v3 >= 0.f ? v3 : 0.2f * v3;
            }
            dst[o0]          = v0;
            dst[o0 + HW]     = v1;
            dst[o0 + 8]      = v2;
            dst[o0 + HW + 8] = v3;
        }
    }
}

// ==================== conv2 (IC=128) + fused instance-norm/SPADE/lrelu ====================
__global__ void __launch_bounds__(128, 2)
k_conv2mma(const float* __restrict__ bg_, const float* __restrict__ bb_,
           float* __restrict__ out) {
    extern __shared__ __align__(1024) char sm[];
    uint32_t sa = smem_u32(sm);
    int tid = threadIdx.x;
    int w = tid >> 5, l = tid & 31;
    int x0 = blockIdx.x * 128, y = blockIdx.y, b = blockIdx.z;
    int mrow = (w & 1) * 64, ncol = (w >> 1) * 64;

    auto stageW = [&](int t1, int buf) {
        int tap = t1 % 9, kc = t1 / 9;
        const char* wg = (const char*)g_w2m + (size_t)(tap * 2 + kc) * 32768;
        for (int idx = tid; idx < 2048; idx += 128) {
            int prec = idx >> 10, e = idx & 1023, oc = e >> 3, ch = e & 7;
            uint32_t d = sa + SW_OFF + buf * WBUF + prec * SW_PREC + oc * 144 + ch * 16;
            CP16(d, wg + idx * 16, 16);
        }
        CP_COMMIT();
    };
    auto stageA = [&](int dy, int kc) {
        int iy = y + dy - 1;
        bool rowok = ((unsigned)iy < 256u);
        int iyc = rowok ? iy : 0;
        for (int idx = tid; idx < 2080; idx += 128) {
            int prec = idx >= 1040; int e = idx - (prec ? 1040 : 0);
            int j = e >> 3, ch = e & 7;
            int x = x0 - 1 + j;
            bool ok = rowok && ((unsigned)x < 256u);
            int xc = ok ? x : 0;
            const __nv_bfloat16* src = prec ? g_actv_l : g_actv_h;
            const void* gp = src + (((size_t)b * HW + iyc * 256 + xc) << 7) + kc * 64 + ch * 8;
            CP16(sa + prec * SA_PREC + j * 144 + ch * 16, gp, ok ? 16 : 0);
        }
        CP_COMMIT();
    };

    float acc[4][8][4];
#pragma unroll
    for (int mt = 0; mt < 4; mt++)
#pragma unroll
        for (int nt = 0; nt < 8; nt++)
#pragma unroll
            for (int e = 0; e < 4; e++) acc[mt][nt][e] = 0.f;

    stageW(0, 0);
    for (int t = 0; t < 18; t++) {
        int kc = t / 9, tap = t % 9;
        int dy = tap / 3, dxk = tap % 3, buf = t & 1;
        __syncthreads();
        if (dxk == 0) stageA(dy, kc);
        if (t < 17) stageW(t + 1, (t + 1) & 1);
        if (t < 17) { CP_WAIT1(); } else { CP_WAIT0(); }
        __syncthreads();

        uint32_t aBase = sa + (mrow + dxk + (l & 15)) * 144 + (l >> 4) * 16;
        uint32_t bBase = sa + SW_OFF + buf * WBUF +
                         (ncol + ((l >> 4) << 3) + (l & 7)) * 144 + ((l >> 3) & 1) * 16;
#pragma unroll
        for (int ks = 0; ks < 4; ks++) {
            uint32_t ah[4][4], al[4][4];
#pragma unroll
            for (int mt = 0; mt < 4; mt++) {
                LDM4(ah[mt], aBase + mt * 16 * 144 + ks * 32);
                LDM4(al[mt], aBase + SA_PREC + mt * 16 * 144 + ks * 32);
            }
#pragma unroll
            for (int np = 0; np < 4; np++) {
                uint32_t bh[4], bl[4];
                LDM4(bh, bBase + np * 16 * 144 + ks * 32);
                LDM4(bl, bBase + SW_PREC + np * 16 * 144 + ks * 32);
#pragma unroll
                for (int mt = 0; mt < 4; mt++) {
                    MMA(acc[mt][np * 2 + 0], ah[mt], bh[0], bh[1]);
                    MMA(acc[mt][np * 2 + 0], ah[mt], bl[0], bl[1]);
                    MMA(acc[mt][np * 2 + 0], al[mt], bh[0], bh[1]);
                    MMA(acc[mt][np * 2 + 1], ah[mt], bh[2], bh[3]);
                    MMA(acc[mt][np * 2 + 1], ah[mt], bl[2], bl[3]);
                    MMA(acc[mt][np * 2 + 1], al[mt], bh[2], bh[3]);
                }
            }
        }
    }

    // exchange acc via smem: sgb[oc'][px], oc' 0-63 = gamma, 64-127 = beta (raw, no bias)
    __syncthreads();
    float* sgb = (float*)sm;  // [128][128] f32 = 64KB (fits in 111744)
    int g = l >> 2, tg = l & 3;
#pragma unroll
    for (int nt = 0; nt < 8; nt++) {
        int c0 = ncol + nt * 8 + tg * 2;
#pragma unroll
        for (int mt = 0; mt < 4; mt++) {
            int pxl = mrow + mt * 16 + g;
            sgb[c0 * 128 + pxl]           = acc[mt][nt][0];
            sgb[(c0 + 1) * 128 + pxl]     = acc[mt][nt][1];
            sgb[c0 * 128 + pxl + 8]       = acc[mt][nt][2];
            sgb[(c0 + 1) * 128 + pxl + 8] = acc[mt][nt][3];
        }
    }
    __syncthreads();

    // fused final: out = lrelu( (dx-mu)*rstd*(1+gamma+bg) + beta+bb )
    for (int r = tid; r < 2048; r += 128) {
        int c = r >> 5, p4 = r & 31;
        float4 ga = *(float4*)&sgb[c * 128 + p4 * 4];
        float4 be = *(float4*)&sgb[(64 + c) * 128 + p4 * 4];
        float bgv = bg_[c], bbv = bb_[c];
        float m = g_stats[b * 64 + c], rs = g_stats[512 + b * 64 + c];
        size_t off = ((size_t)(b * 64 + c)) * HW + y * 256 + x0 + p4 * 4;
        float4 dx = *(const float4*)(g_dx + off);
        float4 o;
        float v;
        v = (dx.x - m) * rs * (1.f + ga.x + bgv) + be.x + bbv; o.x = v >= 0.f ? v : 0.2f * v;
        v = (dx.y - m) * rs * (1.f + ga.y + bgv) + be.y + bbv; o.y = v >= 0.f ? v : 0.2f * v;
        v = (dx.z - m) * rs * (1.f + ga.z + bgv) + be.z + bbv; o.z = v >= 0.f ? v : 0.2f * v;
        v = (dx.w - m) * rs * (1.f + ga.w + bgv) + be.w + bbv; o.w = v >= 0.f ? v : 0.2f * v;
        *(float4*)(out + off) = o;
    }
}

// ==================== instance-norm stats ====================
__global__ void k_stats() {
    int bc = blockIdx.x;
    int tid = threadIdx.x;
    const float4* p = (const float4*)(g_dx + (size_t)bc * HW);
    float s = 0.f, s2 = 0.f;
    for (int i = tid; i < HW / 4; i += 256) {
        float4 v = p[i];
        s  += v.x + v.y + v.z + v.w;
        s2 += v.x * v.x + v.y * v.y + v.z * v.z + v.w * v.w;
    }
    __shared__ float rs[256], rq[256];
    rs[tid] = s; rq[tid] = s2;
    __syncthreads();
    for (int o = 128; o > 0; o >>= 1) {
        if (tid < o) { rs[tid] += rs[tid + o]; rq[tid] += rq[tid + o]; }
        __syncthreads();
    }
    if (tid == 0) {
        float m = rs[0] * (1.f / HW);
        float var = rq[0] * (1.f / HW) - m * m;
        g_stats[bc] = m;
        g_stats[512 + bc] = rsqrtf(var + 1e-5f);
    }
}

// ==================== masked per-class mean pooling ====================
__global__ void k_pool(const int* __restrict__ seg, const float* __restrict__ bg,
                       const float* __restrict__ mask) {
    __shared__ float s_sum[64 * 36];
    __shared__ float s_cnt[36];
    int tid = threadIdx.x;
    for (int i = tid; i < 64 * 36; i += 256) s_sum[i] = 0.f;
    if (tid < 36) s_cnt[tid] = 0.f;
    __syncthreads();
    int b = blockIdx.y;
    int lane = tid & 31, cg = tid >> 5;
    int base = blockIdx.x * 4096;
    for (int p0 = 0; p0 < 4096; p0 += 32) {
        int p = base + p0 + lane;
        int s = seg[b * HW + p];
        bool q = (bg[b * HW + p] * (1.f - mask[b * HW + p])) > 0.f;
        if (q && cg == 0) atomicAdd(&s_cnt[s], 1.f);
        if (q) {
#pragma unroll
            for (int cc = 0; cc < 8; cc++) {
                int c = cg + cc * 8;
                float f = g_feat[((size_t)(b * 64 + c)) * HW + p];
                atomicAdd(&s_sum[c * 36 + s], f);
            }
        }
    }
    __syncthreads();
    for (int i = tid; i < 64 * 36; i += 256) {
        float v = s_sum[i];
        if (v != 0.f) atomicAdd(&g_sums[b * 2304 + i], v);
    }
    if (tid < 36 && s_cnt[tid] != 0.f) atomicAdd(&g_cnt[b * 36 + tid], s_cnt[tid]);
}

__global__ void k_codes() {
    int i = blockIdx.x * 256 + threadIdx.x;
    if (i >= BB * 35 * 64) return;
    int b = i / (35 * 64); int s = (i / 64) % 35; int f = i & 63;
    float cnt = g_cnt[b * 36 + s];
    bool keep = !(s >= 24 && s <= 33);
    float v = 0.f;
    if (cnt > 0.f && keep) v = g_sums[b * 2304 + f * 36 + s] / cnt;
    g_codes[i] = v;
}

__global__ void k_table(const float* __restrict__ w_sh) {
    int b = blockIdx.x / 9, k = blockIdx.x % 9;
    int o = threadIdx.x;  // 128
    __shared__ float swt[64][128];
    __shared__ float sc[64];
    for (int f = 0; f < 64; f++) swt[f][o] = w_sh[(o * 99 + f) * 9 + k];
    for (int s = 0; s < 35; s++) {
        __syncthreads();
        if (o < 64) sc[o] = g_codes[(b * 35 + s) * 64 + o];
        __syncthreads();
        float acc = w_sh[(o * 99 + 64 + s) * 9 + k];
#pragma unroll 8
        for (int f = 0; f < 64; f++)
            acc = fmaf(swt[f][o], sc[f], acc);
        g_table[((b * 9 + k) * 35 + s) * 128 + o] = acc;
    }
}

// ---------------- actv = relu(b_sh + table conv) -> NHWC bf16 hi/lo ----------------
__global__ void k_actv(const int* __restrict__ seg, const float* __restrict__ bg,
                       const float* __restrict__ bsh) {
    __shared__ int ns[324];
    int b = blockIdx.z;
    int x0 = blockIdx.x * 16, y0 = blockIdx.y * 16;
    int tid = threadIdx.x;
    for (int i = tid; i < 324; i += 256) {
        int r = i / 18, c = i % 18;
        int gy = y0 - 1 + r, gx = x0 - 1 + c;
        int v = -1;
        if ((unsigned)gy < 256u && (unsigned)gx < 256u) {
            int p = gy * 256 + gx;
            if (bg[b * HW + p] > 0.f) v = seg[b * HW + p];
        }
        ns[i] = v;
    }
    __syncthreads();
    int oq = tid & 31, pg = tid >> 5;
    const float4* T4 = (const float4*)g_table + (size_t)b * 9 * 35 * 32;
    float4 bias = ((const float4*)bsh)[oq];
    for (int pp = pg * 32; pp < pg * 32 + 32; pp++) {
        int ly = pp >> 4, lx = pp & 15;
        float4 a = bias;
#pragma unroll
        for (int ky = 0; ky < 3; ky++)
#pragma unroll
            for (int kx = 0; kx < 3; kx++) {
                int idx = ns[(ly + ky) * 18 + lx + kx];
                if (idx >= 0) {
                    float4 t = T4[((ky * 3 + kx) * 35 + idx) * 32 + oq];
                    a.x += t.x; a.y += t.y; a.z += t.z; a.w += t.w;
                }
            }
        a.x = fmaxf(a.x, 0.f); a.y = fmaxf(a.y, 0.f);
        a.z = fmaxf(a.z, 0.f); a.w = fmaxf(a.w, 0.f);
        __nv_bfloat16 h0 = __float2bfloat16(a.x), h1 = __float2bfloat16(a.y);
        __nv_bfloat16 h2 = __float2bfloat16(a.z), h3 = __float2bfloat16(a.w);
        __nv_bfloat16 l0 = __float2bfloat16(a.x - __bfloat162float(h0));
        __nv_bfloat16 l1 = __float2bfloat16(a.y - __bfloat162float(h1));
        __nv_bfloat16 l2 = __float2bfloat16(a.z - __bfloat162float(h2));
        __nv_bfloat16 l3 = __float2bfloat16(a.w - __bfloat162float(h3));
        int gp = (y0 + ly) * 256 + x0 + lx;
        size_t base = (((size_t)b * HW + gp) << 7) + oq * 4;
        uint2 hv, lv;
        hv.x = (uint32_t)__bfloat16_as_ushort(h0) | ((uint32_t)__bfloat16_as_ushort(h1) << 16);
        hv.y = (uint32_t)__bfloat16_as_ushort(h2) | ((uint32_t)__bfloat16_as_ushort(h3) << 16);
        lv.x = (uint32_t)__bfloat16_as_ushort(l0) | ((uint32_t)__bfloat16_as_ushort(l1) << 16);
        lv.y = (uint32_t)__bfloat16_as_ushort(l2) | ((uint32_t)__bfloat16_as_ushort(l3) << 16);
        *(uint2*)(g_actv_h + base) = hv;
        *(uint2*)(g_actv_l + base) = lv;
    }
}

// ==================== host ====================
extern "C" void kernel_launch(void* const* d_in, const int* in_sizes, int n_in,
                              void* d_out, int out_size) {
    const float* featmap_in = (const float*)d_in[0];
    const int*   seg        = (const int*)  d_in[1];
    const float* bg         = (const float*)d_in[2];
    const float* mask       = (const float*)d_in[3];
    const float* w_conv     = (const float*)d_in[4];
    const float* b_conv     = (const float*)d_in[5];
    const float* w_c0       = (const float*)d_in[6];
    const float* b_c0       = (const float*)d_in[7];
    const float* w_sh       = (const float*)d_in[8];
    const float* b_sh       = (const float*)d_in[9];
    const float* w_g        = (const float*)d_in[10];
    const float* b_g        = (const float*)d_in[11];
    const float* w_b        = (const float*)d_in[12];
    const float* b_b        = (const float*)d_in[13];

    cudaFuncSetAttribute(k_conv1mma, cudaFuncAttributeMaxDynamicSharedMemorySize, SMEM_MMA);
    cudaFuncSetAttribute(k_conv2mma, cudaFuncAttributeMaxDynamicSharedMemorySize, SMEM_MMA);

    k_zero<<<72, 256>>>();
    k_wpack<<<1152, 256>>>(w_conv, w_c0, w_g, w_b);
    k_split<<<dim3(1024, 8), 256>>>(featmap_in);

    // conv1 (lrelu -> g_feat) + conv_c0 (raw -> g_dx)
    k_conv1mma<<<dim3(2, 256, 8), 128, SMEM_MMA>>>(b_conv, b_c0);

    k_stats<<<512, 256>>>();
    k_pool<<<dim3(16, 8), 256>>>(seg, bg, mask);
    k_codes<<<70, 256>>>();
    k_table<<<72, 128>>>(w_sh);
    k_actv<<<dim3(16, 16, 8), 256>>>(seg, bg, b_sh);

    // gamma/beta conv + fused instance-norm/SPADE/lrelu -> out
    k_conv2mma<<<dim3(2, 256, 8), 128, SMEM_MMA>>>(b_g, b_b, (float*)d_out);
}

// round 13
// speedup vs baseline: 1.2839x; 1.2184x over previous
#include <cuda_runtime.h>
#include <cuda_fp16.h>
#include <cstdint>

#define BB 8
#define HH 256
#define WW 256
#define HW 65536

// ==================== warp-MMA + cp.async helpers (base PTX) ====================
__device__ __forceinline__ uint32_t smem_u32(const void* p) {
    uint32_t a;
    asm("{ .reg .u64 t; cvta.to.shared.u64 t, %1; cvt.u32.u64 %0, t; }" : "=r"(a) : "l"(p));
    return a;
}
#define LDM4(r, addr)                                                              \
    asm volatile("ldmatrix.sync.aligned.m8n8.x4.shared.b16 {%0,%1,%2,%3}, [%4];"   \
        : "=r"((r)[0]), "=r"((r)[1]), "=r"((r)[2]), "=r"((r)[3]) : "r"(addr))
#define MMA(d, a, b0v, b1v)                                                        \
    asm volatile("mma.sync.aligned.m16n8k16.row.col.f32.f16.f16.f32 "              \
        "{%0,%1,%2,%3}, {%4,%5,%6,%7}, {%8,%9}, {%0,%1,%2,%3};"                    \
        : "+f"((d)[0]), "+f"((d)[1]), "+f"((d)[2]), "+f"((d)[3])                   \
        : "r"((a)[0]), "r"((a)[1]), "r"((a)[2]), "r"((a)[3]), "r"(b0v), "r"(b1v))
#define CP16(dst, src, n)                                                          \
    asm volatile("cp.async.cg.shared.global [%0], [%1], 16, %2;"                   \
        :: "r"(dst), "l"(src), "r"(n))
#define CP_COMMIT() asm volatile("cp.async.commit_group;")
#define CP_WAIT1()  asm volatile("cp.async.wait_group 1;")
#define CP_WAIT0()  asm volatile("cp.async.wait_group 0;")

// ==================== scratch ====================
__device__ __align__(128) float g_feat[(size_t)BB * 64 * HW];
__device__ __align__(128) float g_dx  [(size_t)BB * 64 * HW];
__device__ __align__(128) __half g_in  [(size_t)BB * HW * 64];    // NHWC fp16 of featmap_in
__device__ __align__(128) __half g_actv[(size_t)BB * HW * 128];   // NHWC fp16 actv
__device__ __align__(128) float g_table[BB * 9 * 35 * 128];
__device__ __align__(128) float g_codes[BB * 35 * 64];
__device__ __align__(128) float g_sums [BB * 64 * 36];
__device__ __align__(128) float g_cnt  [BB * 36];
__device__ __align__(128) float g_stats[2 * BB * 64];
__device__ __align__(128) __half g_w1m[9 * 2 * 128 * 64];          // [tap][prec][oc'][ic]
__device__ __align__(128) __half g_w2m[9 * 2 * 2 * 128 * 64];      // [tap][kc][prec][oc'][ic]

// ==================== small kernels ====================
__global__ void k_zero() {
    int i = blockIdx.x * 256 + threadIdx.x;
    if (i < BB * 64 * 36) g_sums[i] = 0.f;
    if (i < BB * 36)      g_cnt[i]  = 0.f;
}

__global__ void k_wpack(const float* __restrict__ wc, const float* __restrict__ wc0,
                        const float* __restrict__ wg, const float* __restrict__ wb) {
    int i = blockIdx.x * 256 + threadIdx.x;
    if (i < 9 * 2 * 128 * 64) {
        int ic   = i & 63;
        int oc   = (i >> 6) & 127;
        int prec = (i >> 13) & 1;
        int tap  = i >> 14;
        const float* src = (oc < 64) ? wc : wc0;
        float wv = src[((oc & 63) * 64 + ic) * 9 + tap];
        __half hi = __float2half_rn(wv);
        g_w1m[i] = prec ? __float2half_rn(wv - __half2float(hi)) : hi;
    }
    if (i < 9 * 2 * 2 * 128 * 64) {
        int ic   = i & 63;
        int ocp  = (i >> 6) & 127;
        int prec = (i >> 13) & 1;
        int kc   = (i >> 14) & 1;
        int tap  = i >> 15;
        const float* src = (ocp < 64) ? wg : wb;
        float wv = src[((ocp & 63) * 128 + kc * 64 + ic) * 9 + tap];
        __half hi = __float2half_rn(wv);
        g_w2m[i] = prec ? __float2half_rn(wv - __half2float(hi)) : hi;
    }
}

// NCHW fp32 -> NHWC fp16 (vectorized 8B stores)
__global__ void k_split(const float* __restrict__ in) {
    __shared__ float t[64][65];
    int b = blockIdx.y;
    int p0 = blockIdx.x * 64;
    int tid = threadIdx.x;
    for (int i = tid; i < 64 * 64; i += 256) {
        int c = i >> 6, px = i & 63;
        t[c][px] = in[((size_t)(b * 64 + c)) * HW + p0 + px];
    }
    __syncthreads();
    for (int i = tid; i < 1024; i += 256) {
        int px = i >> 4, c4 = (i & 15) * 4;
        __half h0 = __float2half_rn(t[c4 + 0][px]);
        __half h1 = __float2half_rn(t[c4 + 1][px]);
        __half h2 = __float2half_rn(t[c4 + 2][px]);
        __half h3 = __float2half_rn(t[c4 + 3][px]);
        uint32_t w01 = (uint32_t)__half_as_ushort(h0) | ((uint32_t)__half_as_ushort(h1) << 16);
        uint32_t w23 = (uint32_t)__half_as_ushort(h2) | ((uint32_t)__half_as_ushort(h3) << 16);
        size_t o = (((size_t)b * HW + p0 + px) << 6) + c4;
        *(uint2*)(g_in + o) = make_uint2(w01, w23);
    }
}

// ==================== MMA smem constants ====================
static constexpr int SA_TOT  = 132 * 144;              // 19008 (single precision A)
static constexpr int SW_OFF  = SA_TOT;                 // 19008
static constexpr int SW_PREC = 128 * 144;              // 18432
static constexpr int WBUF    = 2 * SW_PREC;            // 36864 per W buffer
static constexpr int SMEM_MMA = SW_OFF + 2 * WBUF;     // 92736

// ==================== conv1+conv_c0: fp16 2-term, cp.async pipelined ====================
__global__ void __launch_bounds__(128, 2)
k_conv1mma(const float* __restrict__ bc_, const float* __restrict__ bc0_) {
    extern __shared__ __align__(1024) char sm[];
    uint32_t sa = smem_u32(sm);
    int tid = threadIdx.x;
    int w = tid >> 5, l = tid & 31;
    int x0 = blockIdx.x * 128, y = blockIdx.y, b = blockIdx.z;
    int mrow = (w & 1) * 64, ncol = (w >> 1) * 64;

    auto stageW = [&](int tap, int buf) {
        const char* wg = (const char*)g_w1m + (size_t)tap * 32768;
        for (int idx = tid; idx < 2048; idx += 128) {
            int prec = idx >> 10, e = idx & 1023, oc = e >> 3, ch = e & 7;
            uint32_t d = sa + SW_OFF + buf * WBUF + prec * SW_PREC + oc * 144 + ch * 16;
            CP16(d, wg + idx * 16, 16);
        }
        CP_COMMIT();
    };
    auto stageA = [&](int dy) {
        int iy = y + dy - 1;
        bool rowok = ((unsigned)iy < 256u);
        int iyc = rowok ? iy : 0;
        for (int idx = tid; idx < 1040; idx += 128) {
            int j = idx >> 3, ch = idx & 7;
            int x = x0 - 1 + j;
            bool ok = rowok && ((unsigned)x < 256u);
            int xc = ok ? x : 0;
            const void* gp = g_in + (((size_t)b * HW + iyc * 256 + xc) << 6) + ch * 8;
            CP16(sa + j * 144 + ch * 16, gp, ok ? 16 : 0);
        }
        CP_COMMIT();
    };

    float acc[4][8][4];
#pragma unroll
    for (int mt = 0; mt < 4; mt++)
#pragma unroll
        for (int nt = 0; nt < 8; nt++)
#pragma unroll
            for (int e = 0; e < 4; e++) acc[mt][nt][e] = 0.f;

    stageW(0, 0);
    for (int t = 0; t < 9; t++) {
        int dy = t / 3, dxk = t % 3, buf = t & 1;
        __syncthreads();
        if (dxk == 0) stageA(dy);
        if (t < 8) stageW(t + 1, (t + 1) & 1);
        if (t < 8) { CP_WAIT1(); } else { CP_WAIT0(); }
        __syncthreads();

        uint32_t aBase = sa + (mrow + dxk + (l & 15)) * 144 + (l >> 4) * 16;
        uint32_t bBase = sa + SW_OFF + buf * WBUF +
                         (ncol + ((l >> 4) << 3) + (l & 7)) * 144 + ((l >> 3) & 1) * 16;
#pragma unroll
        for (int ks = 0; ks < 4; ks++) {
            uint32_t ah[4][4];
#pragma unroll
            for (int mt = 0; mt < 4; mt++)
                LDM4(ah[mt], aBase + mt * 16 * 144 + ks * 32);
#pragma unroll
            for (int np = 0; np < 4; np++) {
                uint32_t bh[4], bl[4];
                LDM4(bh, bBase + np * 16 * 144 + ks * 32);
                LDM4(bl, bBase + SW_PREC + np * 16 * 144 + ks * 32);
#pragma unroll
                for (int mt = 0; mt < 4; mt++) {
                    MMA(acc[mt][np * 2 + 0], ah[mt], bh[0], bh[1]);
                    MMA(acc[mt][np * 2 + 0], ah[mt], bl[0], bl[1]);
                    MMA(acc[mt][np * 2 + 1], ah[mt], bh[2], bh[3]);
                    MMA(acc[mt][np * 2 + 1], ah[mt], bl[2], bl[3]);
                }
            }
        }
    }

    bool isFeat = (ncol == 0);
    float* dst = isFeat ? g_feat : g_dx;
    const float* bias = isFeat ? bc_ : bc0_;
    int g = l >> 2, tg = l & 3;
#pragma unroll
    for (int nt = 0; nt < 8; nt++) {
        int c0 = (ncol & 63) + nt * 8 + tg * 2;
        float bias0 = bias[c0], bias1 = bias[c0 + 1];
#pragma unroll
        for (int mt = 0; mt < 4; mt++) {
            int px = x0 + mrow + mt * 16 + g;
            size_t o0 = ((size_t)(b * 64 + c0)) * HW + y * 256 + px;
            float v0 = acc[mt][nt][0] + bias0;
            float v1 = acc[mt][nt][1] + bias1;
            float v2 = acc[mt][nt][2] + bias0;
            float v3 = acc[mt][nt][3] + bias1;
            if (isFeat) {
                v0 = v0 >= 0.f ? v0 : 0.2f * v0;
                v1 = v1 >= 0.f ? v1 : 0.2f * v1;
                v2 = v2 >= 0.f ? v2 : 0.2f * v2;
                v3 = v3 >= 0.f ? v3 : 0.2f * v3;
            }
            dst[o0]          = v0;
            dst[o0 + HW]     = v1;
            dst[o0 + 8]      = v2;
            dst[o0 + HW + 8] = v3;
        }
    }
}

// ==================== conv2 (IC=128): fp16 2-term + fused instance-norm/SPADE/lrelu ====================
__global__ void __launch_bounds__(128, 2)
k_conv2mma(const float* __restrict__ bg_, const float* __restrict__ bb_,
           float* __restrict__ out) {
    extern __shared__ __align__(1024) char sm[];
    uint32_t sa = smem_u32(sm);
    int tid = threadIdx.x;
    int w = tid >> 5, l = tid & 31;
    int x0 = blockIdx.x * 128, y = blockIdx.y, b = blockIdx.z;
    int mrow = (w & 1) * 64, ncol = (w >> 1) * 64;

    auto stageW = [&](int t1, int buf) {
        int tap = t1 % 9, kc = t1 / 9;
        const char* wg = (const char*)g_w2m + (size_t)(tap * 2 + kc) * 32768;
        for (int idx = tid; idx < 2048; idx += 128) {
            int prec = idx >> 10, e = idx & 1023, oc = e >> 3, ch = e & 7;
            uint32_t d = sa + SW_OFF + buf * WBUF + prec * SW_PREC + oc * 144 + ch * 16;
            CP16(d, wg + idx * 16, 16);
        }
        CP_COMMIT();
    };
    auto stageA = [&](int dy, int kc) {
        int iy = y + dy - 1;
        bool rowok = ((unsigned)iy < 256u);
        int iyc = rowok ? iy : 0;
        for (int idx = tid; idx < 1040; idx += 128) {
            int j = idx >> 3, ch = idx & 7;
            int x = x0 - 1 + j;
            bool ok = rowok && ((unsigned)x < 256u);
            int xc = ok ? x : 0;
            const void* gp = g_actv + (((size_t)b * HW + iyc * 256 + xc) << 7) + kc * 64 + ch * 8;
            CP16(sa + j * 144 + ch * 16, gp, ok ? 16 : 0);
        }
        CP_COMMIT();
    };

    float acc[4][8][4];
#pragma unroll
    for (int mt = 0; mt < 4; mt++)
#pragma unroll
        for (int nt = 0; nt < 8; nt++)
#pragma unroll
            for (int e = 0; e < 4; e++) acc[mt][nt][e] = 0.f;

    stageW(0, 0);
    for (int t = 0; t < 18; t++) {
        int kc = t / 9, tap = t % 9;
        int dy = tap / 3, dxk = tap % 3, buf = t & 1;
        __syncthreads();
        if (dxk == 0) stageA(dy, kc);
        if (t < 17) stageW(t + 1, (t + 1) & 1);
        if (t < 17) { CP_WAIT1(); } else { CP_WAIT0(); }
        __syncthreads();

        uint32_t aBase = sa + (mrow + dxk + (l & 15)) * 144 + (l >> 4) * 16;
        uint32_t bBase = sa + SW_OFF + buf * WBUF +
                         (ncol + ((l >> 4) << 3) + (l & 7)) * 144 + ((l >> 3) & 1) * 16;
#pragma unroll
        for (int ks = 0; ks < 4; ks++) {
            uint32_t ah[4][4];
#pragma unroll
            for (int mt = 0; mt < 4; mt++)
                LDM4(ah[mt], aBase + mt * 16 * 144 + ks * 32);
#pragma unroll
            for (int np = 0; np < 4; np++) {
                uint32_t bh[4], bl[4];
                LDM4(bh, bBase + np * 16 * 144 + ks * 32);
                LDM4(bl, bBase + SW_PREC + np * 16 * 144 + ks * 32);
#pragma unroll
                for (int mt = 0; mt < 4; mt++) {
                    MMA(acc[mt][np * 2 + 0], ah[mt], bh[0], bh[1]);
                    MMA(acc[mt][np * 2 + 0], ah[mt], bl[0], bl[1]);
                    MMA(acc[mt][np * 2 + 1], ah[mt], bh[2], bh[3]);
                    MMA(acc[mt][np * 2 + 1], ah[mt], bl[2], bl[3]);
                }
            }
        }
    }

    // exchange acc via smem: sgb[oc'][px], oc' 0-63 = gamma, 64-127 = beta (raw)
    __syncthreads();
    float* sgb = (float*)sm;  // [128][128] f32 = 64KB (fits in 92736)
    int g = l >> 2, tg = l & 3;
#pragma unroll
    for (int nt = 0; nt < 8; nt++) {
        int c0 = ncol + nt * 8 + tg * 2;
#pragma unroll
        for (int mt = 0; mt < 4; mt++) {
            int pxl = mrow + mt * 16 + g;
            sgb[c0 * 128 + pxl]           = acc[mt][nt][0];
            sgb[(c0 + 1) * 128 + pxl]     = acc[mt][nt][1];
            sgb[c0 * 128 + pxl + 8]       = acc[mt][nt][2];
            sgb[(c0 + 1) * 128 + pxl + 8] = acc[mt][nt][3];
        }
    }
    __syncthreads();

    // fused final: out = lrelu( (dx-mu)*rstd*(1+gamma+bg) + beta+bb )
    for (int r = tid; r < 2048; r += 128) {
        int c = r >> 5, p4 = r & 31;
        float4 ga = *(float4*)&sgb[c * 128 + p4 * 4];
        float4 be = *(float4*)&sgb[(64 + c) * 128 + p4 * 4];
        float bgv = bg_[c], bbv = bb_[c];
        float m = g_stats[b * 64 + c], rs = g_stats[512 + b * 64 + c];
        size_t off = ((size_t)(b * 64 + c)) * HW + y * 256 + x0 + p4 * 4;
        float4 dx = *(const float4*)(g_dx + off);
        float4 o;
        float v;
        v = (dx.x - m) * rs * (1.f + ga.x + bgv) + be.x + bbv; o.x = v >= 0.f ? v : 0.2f * v;
        v = (dx.y - m) * rs * (1.f + ga.y + bgv) + be.y + bbv; o.y = v >= 0.f ? v : 0.2f * v;
        v = (dx.z - m) * rs * (1.f + ga.z + bgv) + be.z + bbv; o.z = v >= 0.f ? v : 0.2f * v;
        v = (dx.w - m) * rs * (1.f + ga.w + bgv) + be.w + bbv; o.w = v >= 0.f ? v : 0.2f * v;
        *(float4*)(out + off) = o;
    }
}

// ==================== instance-norm stats ====================
__global__ void k_stats() {
    int bc = blockIdx.x;
    int tid = threadIdx.x;
    const float4* p = (const float4*)(g_dx + (size_t)bc * HW);
    float s = 0.f, s2 = 0.f;
    for (int i = tid; i < HW / 4; i += 256) {
        float4 v = p[i];
        s  += v.x + v.y + v.z + v.w;
        s2 += v.x * v.x + v.y * v.y + v.z * v.z + v.w * v.w;
    }
    __shared__ float rs[256], rq[256];
    rs[tid] = s; rq[tid] = s2;
    __syncthreads();
    for (int o = 128; o > 0; o >>= 1) {
        if (tid < o) { rs[tid] += rs[tid + o]; rq[tid] += rq[tid + o]; }
        __syncthreads();
    }
    if (tid == 0) {
        float m = rs[0] * (1.f / HW);
        float var = rq[0] * (1.f / HW) - m * m;
        g_stats[bc] = m;
        g_stats[512 + bc] = rsqrtf(var + 1e-5f);
    }
}

// ==================== masked per-class mean pooling ====================
__global__ void k_pool(const int* __restrict__ seg, const float* __restrict__ bg,
                       const float* __restrict__ mask) {
    __shared__ float s_sum[64 * 36];
    __shared__ float s_cnt[36];
    int tid = threadIdx.x;
    for (int i = tid; i < 64 * 36; i += 256) s_sum[i] = 0.f;
    if (tid < 36) s_cnt[tid] = 0.f;
    __syncthreads();
    int b = blockIdx.y;
    int lane = tid & 31, cg = tid >> 5;
    int base = blockIdx.x * 4096;
    for (int p0 = 0; p0 < 4096; p0 += 32) {
        int p = base + p0 + lane;
        int s = seg[b * HW + p];
        bool q = (bg[b * HW + p] * (1.f - mask[b * HW + p])) > 0.f;
        if (q && cg == 0) atomicAdd(&s_cnt[s], 1.f);
        if (q) {
#pragma unroll
            for (int cc = 0; cc < 8; cc++) {
                int c = cg + cc * 8;
                float f = g_feat[((size_t)(b * 64 + c)) * HW + p];
                atomicAdd(&s_sum[c * 36 + s], f);
            }
        }
    }
    __syncthreads();
    for (int i = tid; i < 64 * 36; i += 256) {
        float v = s_sum[i];
        if (v != 0.f) atomicAdd(&g_sums[b * 2304 + i], v);
    }
    if (tid < 36 && s_cnt[tid] != 0.f) atomicAdd(&g_cnt[b * 36 + tid], s_cnt[tid]);
}

__global__ void k_codes() {
    int i = blockIdx.x * 256 + threadIdx.x;
    if (i >= BB * 35 * 64) return;
    int b = i / (35 * 64); int s = (i / 64) % 35; int f = i & 63;
    float cnt = g_cnt[b * 36 + s];
    bool keep = !(s >= 24 && s <= 33);
    float v = 0.f;
    if (cnt > 0.f && keep) v = g_sums[b * 2304 + f * 36 + s] / cnt;
    g_codes[i] = v;
}

__global__ void k_table(const float* __restrict__ w_sh) {
    int b = blockIdx.x / 9, k = blockIdx.x % 9;
    int o = threadIdx.x;  // 128
    __shared__ float swt[64][128];
    __shared__ float sc[64];
    for (int f = 0; f < 64; f++) swt[f][o] = w_sh[(o * 99 + f) * 9 + k];
    for (int s = 0; s < 35; s++) {
        __syncthreads();
        if (o < 64) sc[o] = g_codes[(b * 35 + s) * 64 + o];
        __syncthreads();
        float acc = w_sh[(o * 99 + 64 + s) * 9 + k];
#pragma unroll 8
        for (int f = 0; f < 64; f++)
            acc = fmaf(swt[f][o], sc[f], acc);
        g_table[((b * 9 + k) * 35 + s) * 128 + o] = acc;
    }
}

// ---------------- actv = relu(b_sh + table conv) -> NHWC fp16 ----------------
__global__ void k_actv(const int* __restrict__ seg, const float* __restrict__ bg,
                       const float* __restrict__ bsh) {
    __shared__ int ns[324];
    int b = blockIdx.z;
    int x0 = blockIdx.x * 16, y0 = blockIdx.y * 16;
    int tid = threadIdx.x;
    for (int i = tid; i < 324; i += 256) {
        int r = i / 18, c = i % 18;
        int gy = y0 - 1 + r, gx = x0 - 1 + c;
        int v = -1;
        if ((unsigned)gy < 256u && (unsigned)gx < 256u) {
            int p = gy * 256 + gx;
            if (bg[b * HW + p] > 0.f) v = seg[b * HW + p];
        }
        ns[i] = v;
    }
    __syncthreads();
    int oq = tid & 31, pg = tid >> 5;
    const float4* T4 = (const float4*)g_table + (size_t)b * 9 * 35 * 32;
    float4 bias = ((const float4*)bsh)[oq];
    for (int pp = pg * 32; pp < pg * 32 + 32; pp++) {
        int ly = pp >> 4, lx = pp & 15;
        float4 a = bias;
#pragma unroll
        for (int ky = 0; ky < 3; ky++)
#pragma unroll
            for (int kx = 0; kx < 3; kx++) {
                int idx = ns[(ly + ky) * 18 + lx + kx];
                if (idx >= 0) {
                    float4 t = T4[((ky * 3 + kx) * 35 + idx) * 32 + oq];
                    a.x += t.x; a.y += t.y; a.z += t.z; a.w += t.w;
                }
            }
        a.x = fmaxf(a.x, 0.f); a.y = fmaxf(a.y, 0.f);
        a.z = fmaxf(a.z, 0.f); a.w = fmaxf(a.w, 0.f);
        __half h0 = __float2half_rn(a.x), h1 = __float2half_rn(a.y);
        __half h2 = __float2half_rn(a.z), h3 = __float2half_rn(a.w);
        uint32_t w01 = (uint32_t)__half_as_ushort(h0) | ((uint32_t)__half_as_ushort(h1) << 16);
        uint32_t w23 = (uint32_t)__half_as_ushort(h2) | ((uint32_t)__half_as_ushort(h3) << 16);
        int gp = (y0 + ly) * 256 + x0 + lx;
        size_t base = (((size_t)b * HW + gp) << 7) + oq * 4;
        *(uint2*)(g_actv + base) = make_uint2(w01, w23);
    }
}

// ==================== host ====================
extern "C" void kernel_launch(void* const* d_in, const int* in_sizes, int n_in,
                              void* d_out, int out_size) {
    const float* featmap_in = (const float*)d_in[0];
    const int*   seg        = (const int*)  d_in[1];
    const float* bg         = (const float*)d_in[2];
    const float* mask       = (const float*)d_in[3];
    const float* w_conv     = (const float*)d_in[4];
    const float* b_conv     = (const float*)d_in[5];
    const float* w_c0       = (const float*)d_in[6];
    const float* b_c0       = (const float*)d_in[7];
    const float* w_sh       = (const float*)d_in[8];
    const float* b_sh       = (const float*)d_in[9];
    const float* w_g        = (const float*)d_in[10];
    const float* b_g        = (const float*)d_in[11];
    const float* w_b        = (const float*)d_in[12];
    const float* b_b        = (const float*)d_in[13];

    cudaFuncSetAttribute(k_conv1mma, cudaFuncAttributeMaxDynamicSharedMemorySize, SMEM_MMA);
    cudaFuncSetAttribute(k_conv2mma, cudaFuncAttributeMaxDynamicSharedMemorySize, SMEM_MMA);

    k_zero<<<72, 256>>>();
    k_wpack<<<1152, 256>>>(w_conv, w_c0, w_g, w_b);
    k_split<<<dim3(1024, 8), 256>>>(featmap_in);

    // conv1 (lrelu -> g_feat) + conv_c0 (raw -> g_dx)
    k_conv1mma<<<dim3(2, 256, 8), 128, SMEM_MMA>>>(b_conv, b_c0);

    k_stats<<<512, 256>>>();
    k_pool<<<dim3(16, 8), 256>>>(seg, bg, mask);
    k_codes<<<70, 256>>>();
    k_table<<<72, 128>>>(w_sh);
    k_actv<<<dim3(16, 16, 8), 256>>>(seg, bg, b_sh);

    // gamma/beta conv + fused instance-norm/SPADE/lrelu -> out
    k_conv2mma<<<dim3(2, 256, 8), 128, SMEM_MMA>>>(b_g, b_b, (float*)d_out);
}

// round 14
// speedup vs baseline: 1.6202x; 1.2619x over previous
#include <cuda_runtime.h>
#include <cuda_fp16.h>
#include <cstdint>

#define BB 8
#define HH 256
#define WW 256
#define HW 65536

// ==================== warp-MMA + cp.async helpers (base PTX) ====================
__device__ __forceinline__ uint32_t smem_u32(const void* p) {
    uint32_t a;
    asm("{ .reg .u64 t; cvta.to.shared.u64 t, %1; cvt.u32.u64 %0, t; }" : "=r"(a) : "l"(p));
    return a;
}
#define LDM4(r, addr)                                                              \
    asm volatile("ldmatrix.sync.aligned.m8n8.x4.shared.b16 {%0,%1,%2,%3}, [%4];"   \
        : "=r"((r)[0]), "=r"((r)[1]), "=r"((r)[2]), "=r"((r)[3]) : "r"(addr))
#define MMA(d, a, b0v, b1v)                                                        \
    asm volatile("mma.sync.aligned.m16n8k16.row.col.f32.f16.f16.f32 "              \
        "{%0,%1,%2,%3}, {%4,%5,%6,%7}, {%8,%9}, {%0,%1,%2,%3};"                    \
        : "+f"((d)[0]), "+f"((d)[1]), "+f"((d)[2]), "+f"((d)[3])                   \
        : "r"((a)[0]), "r"((a)[1]), "r"((a)[2]), "r"((a)[3]), "r"(b0v), "r"(b1v))
#define CP16(dst, src, n)                                                          \
    asm volatile("cp.async.cg.shared.global [%0], [%1], 16, %2;"                   \
        :: "r"(dst), "l"(src), "r"(n))
#define CP_COMMIT() asm volatile("cp.async.commit_group;")
#define CP_WAIT1()  asm volatile("cp.async.wait_group 1;")
#define CP_WAIT0()  asm volatile("cp.async.wait_group 0;")

// ==================== scratch ====================
__device__ __align__(128) float g_feat[(size_t)BB * 64 * HW];
__device__ __align__(128) float g_dx  [(size_t)BB * 64 * HW];
__device__ __align__(128) __half g_in  [(size_t)BB * HW * 64];    // NHWC fp16 of featmap_in
__device__ __align__(128) __half g_actv[(size_t)BB * HW * 128];   // NHWC fp16 actv
__device__ __align__(128) float g_table[BB * 9 * 35 * 128];
__device__ __align__(128) float g_codes[BB * 35 * 64];
__device__ __align__(128) float g_sums [BB * 64 * 36];
__device__ __align__(128) float g_cnt  [BB * 36];
__device__ __align__(128) float g_stats[2 * BB * 64];
__device__ __align__(128) __half g_w1m[9 * 128 * 64];              // [tap][oc'][ic]
__device__ __align__(128) __half g_w2m[9 * 2 * 128 * 64];          // [tap][kc][oc'][ic]

// ==================== small kernels ====================
__global__ void k_zero() {
    int i = blockIdx.x * 256 + threadIdx.x;
    if (i < BB * 64 * 36) g_sums[i] = 0.f;
    if (i < BB * 36)      g_cnt[i]  = 0.f;
}

__global__ void k_wpack(const float* __restrict__ wc, const float* __restrict__ wc0,
                        const float* __restrict__ wg, const float* __restrict__ wb) {
    int i = blockIdx.x * 256 + threadIdx.x;
    if (i < 9 * 128 * 64) {
        int ic  = i & 63;
        int oc  = (i >> 6) & 127;
        int tap = i >> 13;
        const float* src = (oc < 64) ? wc : wc0;
        g_w1m[i] = __float2half_rn(src[((oc & 63) * 64 + ic) * 9 + tap]);
    }
    if (i < 9 * 2 * 128 * 64) {
        int ic  = i & 63;
        int ocp = (i >> 6) & 127;
        int kc  = (i >> 13) & 1;
        int tap = i >> 14;
        const float* src = (ocp < 64) ? wg : wb;
        g_w2m[i] = __float2half_rn(src[((ocp & 63) * 128 + kc * 64 + ic) * 9 + tap]);
    }
}

// NCHW fp32 -> NHWC fp16 (vectorized 8B stores)
__global__ void k_split(const float* __restrict__ in) {
    __shared__ float t[64][65];
    int b = blockIdx.y;
    int p0 = blockIdx.x * 64;
    int tid = threadIdx.x;
    for (int i = tid; i < 64 * 64; i += 256) {
        int c = i >> 6, px = i & 63;
        t[c][px] = in[((size_t)(b * 64 + c)) * HW + p0 + px];
    }
    __syncthreads();
    for (int i = tid; i < 1024; i += 256) {
        int px = i >> 4, c4 = (i & 15) * 4;
        __half h0 = __float2half_rn(t[c4 + 0][px]);
        __half h1 = __float2half_rn(t[c4 + 1][px]);
        __half h2 = __float2half_rn(t[c4 + 2][px]);
        __half h3 = __float2half_rn(t[c4 + 3][px]);
        uint32_t w01 = (uint32_t)__half_as_ushort(h0) | ((uint32_t)__half_as_ushort(h1) << 16);
        uint32_t w23 = (uint32_t)__half_as_ushort(h2) | ((uint32_t)__half_as_ushort(h3) << 16);
        size_t o = (((size_t)b * HW + p0 + px) << 6) + c4;
        *(uint2*)(g_in + o) = make_uint2(w01, w23);
    }
}

// ==================== MMA smem constants ====================
static constexpr int SA_TOT  = 132 * 144;              // 19008 (single precision A)
static constexpr int SW_OFF  = SA_TOT;                 // 19008
static constexpr int WBUF    = 128 * 144;              // 18432 per W buffer (single prec)
static constexpr int SMEM_MMA = SW_OFF + 2 * WBUF;     // 55872

// ==================== conv1+conv_c0: fp16 single-term, cp.async pipelined ====================
__global__ void __launch_bounds__(128, 2)
k_conv1mma(const float* __restrict__ bc_, const float* __restrict__ bc0_) {
    extern __shared__ __align__(1024) char sm[];
    uint32_t sa = smem_u32(sm);
    int tid = threadIdx.x;
    int w = tid >> 5, l = tid & 31;
    int x0 = blockIdx.x * 128, y = blockIdx.y, b = blockIdx.z;
    int mrow = (w & 1) * 64, ncol = (w >> 1) * 64;

    auto stageW = [&](int tap, int buf) {
        const char* wg = (const char*)g_w1m + (size_t)tap * 16384;
        for (int idx = tid; idx < 1024; idx += 128) {
            int oc = idx >> 3, ch = idx & 7;
            uint32_t d = sa + SW_OFF + buf * WBUF + oc * 144 + ch * 16;
            CP16(d, wg + idx * 16, 16);
        }
        CP_COMMIT();
    };
    auto stageA = [&](int dy) {
        int iy = y + dy - 1;
        bool rowok = ((unsigned)iy < 256u);
        int iyc = rowok ? iy : 0;
        for (int idx = tid; idx < 1040; idx += 128) {
            int j = idx >> 3, ch = idx & 7;
            int x = x0 - 1 + j;
            bool ok = rowok && ((unsigned)x < 256u);
            int xc = ok ? x : 0;
            const void* gp = g_in + (((size_t)b * HW + iyc * 256 + xc) << 6) + ch * 8;
            CP16(sa + j * 144 + ch * 16, gp, ok ? 16 : 0);
        }
        CP_COMMIT();
    };

    float acc[4][8][4];
#pragma unroll
    for (int mt = 0; mt < 4; mt++)
#pragma unroll
        for (int nt = 0; nt < 8; nt++)
#pragma unroll
            for (int e = 0; e < 4; e++) acc[mt][nt][e] = 0.f;

    stageW(0, 0);
    for (int t = 0; t < 9; t++) {
        int dy = t / 3, dxk = t % 3, buf = t & 1;
        __syncthreads();
        if (dxk == 0) stageA(dy);
        if (t < 8) stageW(t + 1, (t + 1) & 1);
        if (t < 8) { CP_WAIT1(); } else { CP_WAIT0(); }
        __syncthreads();

        uint32_t aBase = sa + (mrow + dxk + (l & 15)) * 144 + (l >> 4) * 16;
        uint32_t bBase = sa + SW_OFF + buf * WBUF +
                         (ncol + ((l >> 4) << 3) + (l & 7)) * 144 + ((l >> 3) & 1) * 16;
#pragma unroll
        for (int ks = 0; ks < 4; ks++) {
            uint32_t ah[4][4];
#pragma unroll
            for (int mt = 0; mt < 4; mt++)
                LDM4(ah[mt], aBase + mt * 16 * 144 + ks * 32);
#pragma unroll
            for (int np = 0; np < 4; np++) {
                uint32_t bh[4];
                LDM4(bh, bBase + np * 16 * 144 + ks * 32);
#pragma unroll
                for (int mt = 0; mt < 4; mt++) {
                    MMA(acc[mt][np * 2 + 0], ah[mt], bh[0], bh[1]);
                    MMA(acc[mt][np * 2 + 1], ah[mt], bh[2], bh[3]);
                }
            }
        }
    }

    bool isFeat = (ncol == 0);
    float* dst = isFeat ? g_feat : g_dx;
    const float* bias = isFeat ? bc_ : bc0_;
    int g = l >> 2, tg = l & 3;
#pragma unroll
    for (int nt = 0; nt < 8; nt++) {
        int c0 = (ncol & 63) + nt * 8 + tg * 2;
        float bias0 = bias[c0], bias1 = bias[c0 + 1];
#pragma unroll
        for (int mt = 0; mt < 4; mt++) {
            int px = x0 + mrow + mt * 16 + g;
            size_t o0 = ((size_t)(b * 64 + c0)) * HW + y * 256 + px;
            float v0 = acc[mt][nt][0] + bias0;
            float v1 = acc[mt][nt][1] + bias1;
            float v2 = acc[mt][nt][2] + bias0;
            float v3 = acc[mt][nt][3] + bias1;
            if (isFeat) {
                v0 = v0 >= 0.f ? v0 : 0.2f * v0;
                v1 = v1 >= 0.f ? v1 : 0.2f * v1;
                v2 = v2 >= 0.f ? v2 : 0.2f * v2;
                v3 = v3 >= 0.f ? v3 : 0.2f * v3;
            }
            dst[o0]          = v0;
            dst[o0 + HW]     = v1;
            dst[o0 + 8]      = v2;
            dst[o0 + HW + 8] = v3;
        }
    }
}

// ==================== conv2 (IC=128): fp16 single-term + fused final ====================
__global__ void __launch_bounds__(128, 2)
k_conv2mma(const float* __restrict__ bg_, const float* __restrict__ bb_,
           float* __restrict__ out) {
    extern __shared__ __align__(1024) char sm[];
    uint32_t sa = smem_u32(sm);
    int tid = threadIdx.x;
    int w = tid >> 5, l = tid & 31;
    int x0 = blockIdx.x * 128, y = blockIdx.y, b = blockIdx.z;
    int mrow = (w & 1) * 64, ncol = (w >> 1) * 64;

    auto stageW = [&](int t1, int buf) {
        int tap = t1 % 9, kc = t1 / 9;
        const char* wg = (const char*)g_w2m + (size_t)(tap * 2 + kc) * 16384;
        for (int idx = tid; idx < 1024; idx += 128) {
            int oc = idx >> 3, ch = idx & 7;
            uint32_t d = sa + SW_OFF + buf * WBUF + oc * 144 + ch * 16;
            CP16(d, wg + idx * 16, 16);
        }
        CP_COMMIT();
    };
    auto stageA = [&](int dy, int kc) {
        int iy = y + dy - 1;
        bool rowok = ((unsigned)iy < 256u);
        int iyc = rowok ? iy : 0;
        for (int idx = tid; idx < 1040; idx += 128) {
            int j = idx >> 3, ch = idx & 7;
            int x = x0 - 1 + j;
            bool ok = rowok && ((unsigned)x < 256u);
            int xc = ok ? x : 0;
            const void* gp = g_actv + (((size_t)b * HW + iyc * 256 + xc) << 7) + kc * 64 + ch * 8;
            CP16(sa + j * 144 + ch * 16, gp, ok ? 16 : 0);
        }
        CP_COMMIT();
    };

    float acc[4][8][4];
#pragma unroll
    for (int mt = 0; mt < 4; mt++)
#pragma unroll
        for (int nt = 0; nt < 8; nt++)
#pragma unroll
            for (int e = 0; e < 4; e++) acc[mt][nt][e] = 0.f;

    stageW(0, 0);
    for (int t = 0; t < 18; t++) {
        int kc = t / 9, tap = t % 9;
        int dy = tap / 3, dxk = tap % 3, buf = t & 1;
        __syncthreads();
        if (dxk == 0) stageA(dy, kc);
        if (t < 17) stageW(t + 1, (t + 1) & 1);
        if (t < 17) { CP_WAIT1(); } else { CP_WAIT0(); }
        __syncthreads();

        uint32_t aBase = sa + (mrow + dxk + (l & 15)) * 144 + (l >> 4) * 16;
        uint32_t bBase = sa + SW_OFF + buf * WBUF +
                         (ncol + ((l >> 4) << 3) + (l & 7)) * 144 + ((l >> 3) & 1) * 16;
#pragma unroll
        for (int ks = 0; ks < 4; ks++) {
            uint32_t ah[4][4];
#pragma unroll
            for (int mt = 0; mt < 4; mt++)
                LDM4(ah[mt], aBase + mt * 16 * 144 + ks * 32);
#pragma unroll
            for (int np = 0; np < 4; np++) {
                uint32_t bh[4];
                LDM4(bh, bBase + np * 16 * 144 + ks * 32);
#pragma unroll
                for (int mt = 0; mt < 4; mt++) {
                    MMA(acc[mt][np * 2 + 0], ah[mt], bh[0], bh[1]);
                    MMA(acc[mt][np * 2 + 1], ah[mt], bh[2], bh[3]);
                }
            }
        }
    }

    // exchange acc via smem: sgb[oc'][px], oc' 0-63 = gamma, 64-127 = beta (raw)
    __syncthreads();
    float* sgb = (float*)sm;  // need 64KB; SMEM_MMA=55872 -> use max(SMEM_MMA, 65536)
    int g = l >> 2, tg = l & 3;
#pragma unroll
    for (int nt = 0; nt < 8; nt++) {
        int c0 = ncol + nt * 8 + tg * 2;
#pragma unroll
        for (int mt = 0; mt < 4; mt++) {
            int pxl = mrow + mt * 16 + g;
            sgb[c0 * 128 + pxl]           = acc[mt][nt][0];
            sgb[(c0 + 1) * 128 + pxl]     = acc[mt][nt][1];
            sgb[c0 * 128 + pxl + 8]       = acc[mt][nt][2];
            sgb[(c0 + 1) * 128 + pxl + 8] = acc[mt][nt][3];
        }
    }
    __syncthreads();

    // fused final: out = lrelu( (dx-mu)*rstd*(1+gamma+bg) + beta+bb )
    for (int r = tid; r < 2048; r += 128) {
        int c = r >> 5, p4 = r & 31;
        float4 ga = *(float4*)&sgb[c * 128 + p4 * 4];
        float4 be = *(float4*)&sgb[(64 + c) * 128 + p4 * 4];
        float bgv = bg_[c], bbv = bb_[c];
        float m = g_stats[b * 64 + c], rs = g_stats[512 + b * 64 + c];
        size_t off = ((size_t)(b * 64 + c)) * HW + y * 256 + x0 + p4 * 4;
        float4 dx = *(const float4*)(g_dx + off);
        float4 o;
        float v;
        v = (dx.x - m) * rs * (1.f + ga.x + bgv) + be.x + bbv; o.x = v >= 0.f ? v : 0.2f * v;
        v = (dx.y - m) * rs * (1.f + ga.y + bgv) + be.y + bbv; o.y = v >= 0.f ? v : 0.2f * v;
        v = (dx.z - m) * rs * (1.f + ga.z + bgv) + be.z + bbv; o.z = v >= 0.f ? v : 0.2f * v;
        v = (dx.w - m) * rs * (1.f + ga.w + bgv) + be.w + bbv; o.w = v >= 0.f ? v : 0.2f * v;
        *(float4*)(out + off) = o;
    }
}

// ==================== instance-norm stats ====================
__global__ void k_stats() {
    int bc = blockIdx.x;
    int tid = threadIdx.x;
    const float4* p = (const float4*)(g_dx + (size_t)bc * HW);
    float s = 0.f, s2 = 0.f;
    for (int i = tid; i < HW / 4; i += 256) {
        float4 v = p[i];
        s  += v.x + v.y + v.z + v.w;
        s2 += v.x * v.x + v.y * v.y + v.z * v.z + v.w * v.w;
    }
    __shared__ float rs[256], rq[256];
    rs[tid] = s; rq[tid] = s2;
    __syncthreads();
    for (int o = 128; o > 0; o >>= 1) {
        if (tid < o) { rs[tid] += rs[tid + o]; rq[tid] += rq[tid + o]; }
        __syncthreads();
    }
    if (tid == 0) {
        float m = rs[0] * (1.f / HW);
        float var = rq[0] * (1.f / HW) - m * m;
        g_stats[bc] = m;
        g_stats[512 + bc] = rsqrtf(var + 1e-5f);
    }
}

// ==================== masked per-class mean pooling ====================
__global__ void k_pool(const int* __restrict__ seg, const float* __restrict__ bg,
                       const float* __restrict__ mask) {
    __shared__ float s_sum[64 * 36];
    __shared__ float s_cnt[36];
    int tid = threadIdx.x;
    for (int i = tid; i < 64 * 36; i += 256) s_sum[i] = 0.f;
    if (tid < 36) s_cnt[tid] = 0.f;
    __syncthreads();
    int b = blockIdx.y;
    int lane = tid & 31, cg = tid >> 5;
    int base = blockIdx.x * 4096;
    for (int p0 = 0; p0 < 4096; p0 += 32) {
        int p = base + p0 + lane;
        int s = seg[b * HW + p];
        bool q = (bg[b * HW + p] * (1.f - mask[b * HW + p])) > 0.f;
        if (q && cg == 0) atomicAdd(&s_cnt[s], 1.f);
        if (q) {
#pragma unroll
            for (int cc = 0; cc < 8; cc++) {
                int c = cg + cc * 8;
                float f = g_feat[((size_t)(b * 64 + c)) * HW + p];
                atomicAdd(&s_sum[c * 36 + s], f);
            }
        }
    }
    __syncthreads();
    for (int i = tid; i < 64 * 36; i += 256) {
        float v = s_sum[i];
        if (v != 0.f) atomicAdd(&g_sums[b * 2304 + i], v);
    }
    if (tid < 36 && s_cnt[tid] != 0.f) atomicAdd(&g_cnt[b * 36 + tid], s_cnt[tid]);
}

__global__ void k_codes() {
    int i = blockIdx.x * 256 + threadIdx.x;
    if (i >= BB * 35 * 64) return;
    int b = i / (35 * 64); int s = (i / 64) % 35; int f = i & 63;
    float cnt = g_cnt[b * 36 + s];
    bool keep = !(s >= 24 && s <= 33);
    float v = 0.f;
    if (cnt > 0.f && keep) v = g_sums[b * 2304 + f * 36 + s] / cnt;
    g_codes[i] = v;
}

__global__ void k_table(const float* __restrict__ w_sh) {
    int b = blockIdx.x / 9, k = blockIdx.x % 9;
    int o = threadIdx.x;  // 128
    __shared__ float swt[64][128];
    __shared__ float sc[64];
    for (int f = 0; f < 64; f++) swt[f][o] = w_sh[(o * 99 + f) * 9 + k];
    for (int s = 0; s < 35; s++) {
        __syncthreads();
        if (o < 64) sc[o] = g_codes[(b * 35 + s) * 64 + o];
        __syncthreads();
        float acc = w_sh[(o * 99 + 64 + s) * 9 + k];
#pragma unroll 8
        for (int f = 0; f < 64; f++)
            acc = fmaf(swt[f][o], sc[f], acc);
        g_table[((b * 9 + k) * 35 + s) * 128 + o] = acc;
    }
}

// ---------------- actv = relu(b_sh + table conv) -> NHWC fp16 ----------------
__global__ void k_actv(const int* __restrict__ seg, const float* __restrict__ bg,
                       const float* __restrict__ bsh) {
    __shared__ int ns[324];
    int b = blockIdx.z;
    int x0 = blockIdx.x * 16, y0 = blockIdx.y * 16;
    int tid = threadIdx.x;
    for (int i = tid; i < 324; i += 256) {
        int r = i / 18, c = i % 18;
        int gy = y0 - 1 + r, gx = x0 - 1 + c;
        int v = -1;
        if ((unsigned)gy < 256u && (unsigned)gx < 256u) {
            int p = gy * 256 + gx;
            if (bg[b * HW + p] > 0.f) v = seg[b * HW + p];
        }
        ns[i] = v;
    }
    __syncthreads();
    int oq = tid & 31, pg = tid >> 5;
    const float4* T4 = (const float4*)g_table + (size_t)b * 9 * 35 * 32;
    float4 bias = ((const float4*)bsh)[oq];
    for (int pp = pg * 32; pp < pg * 32 + 32; pp++) {
        int ly = pp >> 4, lx = pp & 15;
        float4 a = bias;
#pragma unroll
        for (int ky = 0; ky < 3; ky++)
#pragma unroll
            for (int kx = 0; kx < 3; kx++) {
                int idx = ns[(ly + ky) * 18 + lx + kx];
                if (idx >= 0) {
                    float4 t = T4[((ky * 3 + kx) * 35 + idx) * 32 + oq];
                    a.x += t.x; a.y += t.y; a.z += t.z; a.w += t.w;
                }
            }
        a.x = fmaxf(a.x, 0.f); a.y = fmaxf(a.y, 0.f);
        a.z = fmaxf(a.z, 0.f); a.w = fmaxf(a.w, 0.f);
        __half h0 = __float2half_rn(a.x), h1 = __float2half_rn(a.y);
        __half h2 = __float2half_rn(a.z), h3 = __float2half_rn(a.w);
        uint32_t w01 = (uint32_t)__half_as_ushort(h0) | ((uint32_t)__half_as_ushort(h1) << 16);
        uint32_t w23 = (uint32_t)__half_as_ushort(h2) | ((uint32_t)__half_as_ushort(h3) << 16);
        int gp = (y0 + ly) * 256 + x0 + lx;
        size_t base = (((size_t)b * HW + gp) << 7) + oq * 4;
        *(uint2*)(g_actv + base) = make_uint2(w01, w23);
    }
}

// ==================== host ====================
extern "C" void kernel_launch(void* const* d_in, const int* in_sizes, int n_in,
                              void* d_out, int out_size) {
    const float* featmap_in = (const float*)d_in[0];
    const int*   seg        = (const int*)  d_in[1];
    const float* bg         = (const float*)d_in[2];
    const float* mask       = (const float*)d_in[3];
    const float* w_conv     = (const float*)d_in[4];
    const float* b_conv     = (const float*)d_in[5];
    const float* w_c0       = (const float*)d_in[6];
    const float* b_c0       = (const float*)d_in[7];
    const float* w_sh       = (const float*)d_in[8];
    const float* b_sh       = (const float*)d_in[9];
    const float* w_g        = (const float*)d_in[10];
    const float* b_g        = (const float*)d_in[11];
    const float* w_b        = (const float*)d_in[12];
    const float* b_b        = (const float*)d_in[13];

    const int SMEM1 = SMEM_MMA;                       // 55872
    const int SMEM2 = (SMEM_MMA > 65536) ? SMEM_MMA : 65536;  // conv2 needs 64KB sgb
    cudaFuncSetAttribute(k_conv1mma, cudaFuncAttributeMaxDynamicSharedMemorySize, SMEM1);
    cudaFuncSetAttribute(k_conv2mma, cudaFuncAttributeMaxDynamicSharedMemorySize, SMEM2);

    k_zero<<<72, 256>>>();
    k_wpack<<<576, 256>>>(w_conv, w_c0, w_g, w_b);
    k_split<<<dim3(1024, 8), 256>>>(featmap_in);

    // conv1 (lrelu -> g_feat) + conv_c0 (raw -> g_dx)
    k_conv1mma<<<dim3(2, 256, 8), 128, SMEM1>>>(b_conv, b_c0);

    k_stats<<<512, 256>>>();
    k_pool<<<dim3(16, 8), 256>>>(seg, bg, mask);
    k_codes<<<70, 256>>>();
    k_table<<<72, 128>>>(w_sh);
    k_actv<<<dim3(16, 16, 8), 256>>>(seg, bg, b_sh);

    // gamma/beta conv + fused instance-norm/SPADE/lrelu -> out
    k_conv2mma<<<dim3(2, 256, 8), 128, SMEM2>>>(b_g, b_b, (float*)d_out);
}

// round 15
// speedup vs baseline: 1.6821x; 1.0382x over previous
#include <cuda_runtime.h>
#include <cuda_fp16.h>
#include <cstdint>

#define BB 8
#define HH 256
#define WW 256
#define HW 65536

// ==================== warp-MMA + cp.async helpers (base PTX) ====================
__device__ __forceinline__ uint32_t smem_u32(const void* p) {
    uint32_t a;
    asm("{ .reg .u64 t; cvta.to.shared.u64 t, %1; cvt.u32.u64 %0, t; }" : "=r"(a) : "l"(p));
    return a;
}
#define LDM4(r, addr)                                                              \
    asm volatile("ldmatrix.sync.aligned.m8n8.x4.shared.b16 {%0,%1,%2,%3}, [%4];"   \
        : "=r"((r)[0]), "=r"((r)[1]), "=r"((r)[2]), "=r"((r)[3]) : "r"(addr))
#define MMA(d, a, b0v, b1v)                                                        \
    asm volatile("mma.sync.aligned.m16n8k16.row.col.f32.f16.f16.f32 "              \
        "{%0,%1,%2,%3}, {%4,%5,%6,%7}, {%8,%9}, {%0,%1,%2,%3};"                    \
        : "+f"((d)[0]), "+f"((d)[1]), "+f"((d)[2]), "+f"((d)[3])                   \
        : "r"((a)[0]), "r"((a)[1]), "r"((a)[2]), "r"((a)[3]), "r"(b0v), "r"(b1v))
#define CP16(dst, src, n)                                                          \
    asm volatile("cp.async.cg.shared.global [%0], [%1], 16, %2;"                   \
        :: "r"(dst), "l"(src), "r"(n))
#define CP_COMMIT() asm volatile("cp.async.commit_group;")
#define CP_WAIT1()  asm volatile("cp.async.wait_group 1;")
#define CP_WAIT0()  asm volatile("cp.async.wait_group 0;")

// ==================== scratch ====================
__device__ __align__(128) float g_feat[(size_t)BB * 64 * HW];
__device__ __align__(128) float g_dx  [(size_t)BB * 64 * HW];
__device__ __align__(128) __half g_in  [(size_t)BB * HW * 64];    // NHWC fp16 of featmap_in
__device__ __align__(128) __half g_actv[(size_t)BB * HW * 128];   // NHWC fp16 actv
__device__ __align__(128) float g_table[BB * 9 * 35 * 128];
__device__ __align__(128) float g_codes[BB * 35 * 64];
__device__ __align__(128) float g_sums [BB * 64 * 36];
__device__ __align__(128) float g_cnt  [BB * 36];
__device__ __align__(128) float g_stats[2 * BB * 64];
__device__ __align__(128) __half g_w1m[9 * 128 * 64];              // [tap][oc'][ic]
__device__ __align__(128) __half g_w2m[9 * 128 * 128];             // [tap][oc'][ic 0-127]

// ==================== small kernels ====================
__global__ void k_zero() {
    int i = blockIdx.x * 256 + threadIdx.x;
    if (i < BB * 64 * 36) g_sums[i] = 0.f;
    if (i < BB * 36)      g_cnt[i]  = 0.f;
}

__global__ void k_wpack(const float* __restrict__ wc, const float* __restrict__ wc0,
                        const float* __restrict__ wg, const float* __restrict__ wb) {
    int i = blockIdx.x * 256 + threadIdx.x;
    if (i < 9 * 128 * 64) {
        int ic  = i & 63;
        int oc  = (i >> 6) & 127;
        int tap = i >> 13;
        const float* src = (oc < 64) ? wc : wc0;
        g_w1m[i] = __float2half_rn(src[((oc & 63) * 64 + ic) * 9 + tap]);
    }
    if (i < 9 * 128 * 128) {
        int ic  = i & 127;
        int ocp = (i >> 7) & 127;
        int tap = i >> 14;
        const float* src = (ocp < 64) ? wg : wb;
        g_w2m[i] = __float2half_rn(src[((ocp & 63) * 128 + ic) * 9 + tap]);
    }
}

// NCHW fp32 -> NHWC fp16 (vectorized 8B stores)
__global__ void k_split(const float* __restrict__ in) {
    __shared__ float t[64][65];
    int b = blockIdx.y;
    int p0 = blockIdx.x * 64;
    int tid = threadIdx.x;
    for (int i = tid; i < 64 * 64; i += 256) {
        int c = i >> 6, px = i & 63;
        t[c][px] = in[((size_t)(b * 64 + c)) * HW + p0 + px];
    }
    __syncthreads();
    for (int i = tid; i < 1024; i += 256) {
        int px = i >> 4, c4 = (i & 15) * 4;
        __half h0 = __float2half_rn(t[c4 + 0][px]);
        __half h1 = __float2half_rn(t[c4 + 1][px]);
        __half h2 = __float2half_rn(t[c4 + 2][px]);
        __half h3 = __float2half_rn(t[c4 + 3][px]);
        uint32_t w01 = (uint32_t)__half_as_ushort(h0) | ((uint32_t)__half_as_ushort(h1) << 16);
        uint32_t w23 = (uint32_t)__half_as_ushort(h2) | ((uint32_t)__half_as_ushort(h3) << 16);
        size_t o = (((size_t)b * HW + p0 + px) << 6) + c4;
        *(uint2*)(g_in + o) = make_uint2(w01, w23);
    }
}

// ==================== conv1 smem constants (K=64 rows, 144B stride) ====================
static constexpr int SA_TOT  = 132 * 144;              // 19008
static constexpr int SW_OFF  = SA_TOT;                 // 19008
static constexpr int WBUF    = 128 * 144;              // 18432
static constexpr int SMEM_C1 = SW_OFF + 2 * WBUF;      // 55872

// ==================== conv2 smem constants (K=128 rows, 272B stride) ====================
static constexpr int SA2     = 132 * 272;              // 35904
static constexpr int SW_OFF2 = SA2;                    // 35904
static constexpr int WBUF2   = 128 * 272;              // 34816
static constexpr int SMEM_C2 = SW_OFF2 + 2 * WBUF2;    // 105536

// ==================== conv1+conv_c0: fp16 single-term, cp.async pipelined ====================
__global__ void __launch_bounds__(128, 2)
k_conv1mma(const float* __restrict__ bc_, const float* __restrict__ bc0_) {
    extern __shared__ __align__(1024) char sm[];
    uint32_t sa = smem_u32(sm);
    int tid = threadIdx.x;
    int w = tid >> 5, l = tid & 31;
    int x0 = blockIdx.x * 128, y = blockIdx.y, b = blockIdx.z;
    int mrow = (w & 1) * 64, ncol = (w >> 1) * 64;

    auto stageW = [&](int tap, int buf) {
        const char* wg = (const char*)g_w1m + (size_t)tap * 16384;
        for (int idx = tid; idx < 1024; idx += 128) {
            int oc = idx >> 3, ch = idx & 7;
            uint32_t d = sa + SW_OFF + buf * WBUF + oc * 144 + ch * 16;
            CP16(d, wg + idx * 16, 16);
        }
        CP_COMMIT();
    };
    auto stageA = [&](int dy) {
        int iy = y + dy - 1;
        bool rowok = ((unsigned)iy < 256u);
        int iyc = rowok ? iy : 0;
        for (int idx = tid; idx < 1040; idx += 128) {
            int j = idx >> 3, ch = idx & 7;
            int x = x0 - 1 + j;
            bool ok = rowok && ((unsigned)x < 256u);
            int xc = ok ? x : 0;
            const void* gp = g_in + (((size_t)b * HW + iyc * 256 + xc) << 6) + ch * 8;
            CP16(sa + j * 144 + ch * 16, gp, ok ? 16 : 0);
        }
        CP_COMMIT();
    };

    float acc[4][8][4];
#pragma unroll
    for (int mt = 0; mt < 4; mt++)
#pragma unroll
        for (int nt = 0; nt < 8; nt++)
#pragma unroll
            for (int e = 0; e < 4; e++) acc[mt][nt][e] = 0.f;

    stageW(0, 0);
    for (int t = 0; t < 9; t++) {
        int dy = t / 3, dxk = t % 3, buf = t & 1;
        __syncthreads();
        if (dxk == 0) stageA(dy);
        if (t < 8) stageW(t + 1, (t + 1) & 1);
        if (t < 8) { CP_WAIT1(); } else { CP_WAIT0(); }
        __syncthreads();

        uint32_t aBase = sa + (mrow + dxk + (l & 15)) * 144 + (l >> 4) * 16;
        uint32_t bBase = sa + SW_OFF + buf * WBUF +
                         (ncol + ((l >> 4) << 3) + (l & 7)) * 144 + ((l >> 3) & 1) * 16;
#pragma unroll
        for (int ks = 0; ks < 4; ks++) {
            uint32_t ah[4][4];
#pragma unroll
            for (int mt = 0; mt < 4; mt++)
                LDM4(ah[mt], aBase + mt * 16 * 144 + ks * 32);
#pragma unroll
            for (int np = 0; np < 4; np++) {
                uint32_t bh[4];
                LDM4(bh, bBase + np * 16 * 144 + ks * 32);
#pragma unroll
                for (int mt = 0; mt < 4; mt++) {
                    MMA(acc[mt][np * 2 + 0], ah[mt], bh[0], bh[1]);
                    MMA(acc[mt][np * 2 + 1], ah[mt], bh[2], bh[3]);
                }
            }
        }
    }

    bool isFeat = (ncol == 0);
    float* dst = isFeat ? g_feat : g_dx;
    const float* bias = isFeat ? bc_ : bc0_;
    int g = l >> 2, tg = l & 3;
#pragma unroll
    for (int nt = 0; nt < 8; nt++) {
        int c0 = (ncol & 63) + nt * 8 + tg * 2;
        float bias0 = bias[c0], bias1 = bias[c0 + 1];
#pragma unroll
        for (int mt = 0; mt < 4; mt++) {
            int px = x0 + mrow + mt * 16 + g;
            size_t o0 = ((size_t)(b * 64 + c0)) * HW + y * 256 + px;
            float v0 = acc[mt][nt][0] + bias0;
            float v1 = acc[mt][nt][1] + bias1;
            float v2 = acc[mt][nt][2] + bias0;
            float v3 = acc[mt][nt][3] + bias1;
            if (isFeat) {
                v0 = v0 >= 0.f ? v0 : 0.2f * v0;
                v1 = v1 >= 0.f ? v1 : 0.2f * v1;
                v2 = v2 >= 0.f ? v2 : 0.2f * v2;
                v3 = v3 >= 0.f ? v3 : 0.2f * v3;
            }
            dst[o0]          = v0;
            dst[o0 + HW]     = v1;
            dst[o0 + 8]      = v2;
            dst[o0 + HW + 8] = v3;
        }
    }
}

// ==================== conv2: K=128 rows, 9 stages, fused final ====================
__global__ void __launch_bounds__(128, 2)
k_conv2mma(const float* __restrict__ bg_, const float* __restrict__ bb_,
           float* __restrict__ out) {
    extern __shared__ __align__(1024) char sm[];
    uint32_t sa = smem_u32(sm);
    int tid = threadIdx.x;
    int w = tid >> 5, l = tid & 31;
    int x0 = blockIdx.x * 128, y = blockIdx.y, b = blockIdx.z;
    int mrow = (w & 1) * 64, ncol = (w >> 1) * 64;

    auto stageW = [&](int tap, int buf) {
        const char* wg = (const char*)g_w2m + (size_t)tap * 32768;
        for (int idx = tid; idx < 2048; idx += 128) {
            int oc = idx >> 4, ch = idx & 15;
            uint32_t d = sa + SW_OFF2 + buf * WBUF2 + oc * 272 + ch * 16;
            CP16(d, wg + idx * 16, 16);
        }
        CP_COMMIT();
    };
    auto stageA = [&](int dy) {
        int iy = y + dy - 1;
        bool rowok = ((unsigned)iy < 256u);
        int iyc = rowok ? iy : 0;
        for (int idx = tid; idx < 2080; idx += 128) {
            int j = idx >> 4, ch = idx & 15;
            int x = x0 - 1 + j;
            bool ok = rowok && ((unsigned)x < 256u);
            int xc = ok ? x : 0;
            const void* gp = g_actv + (((size_t)b * HW + iyc * 256 + xc) << 7) + ch * 8;
            CP16(sa + j * 272 + ch * 16, gp, ok ? 16 : 0);
        }
        CP_COMMIT();
    };

    float acc[4][8][4];
#pragma unroll
    for (int mt = 0; mt < 4; mt++)
#pragma unroll
        for (int nt = 0; nt < 8; nt++)
#pragma unroll
            for (int e = 0; e < 4; e++) acc[mt][nt][e] = 0.f;

    stageW(0, 0);
    for (int t = 0; t < 9; t++) {
        int dy = t / 3, dxk = t % 3, buf = t & 1;
        __syncthreads();
        if (dxk == 0) stageA(dy);
        if (t < 8) stageW(t + 1, (t + 1) & 1);
        if (t < 8) { CP_WAIT1(); } else { CP_WAIT0(); }
        __syncthreads();

        uint32_t aBase = sa + (mrow + dxk + (l & 15)) * 272 + (l >> 4) * 16;
        uint32_t bBase = sa + SW_OFF2 + buf * WBUF2 +
                         (ncol + ((l >> 4) << 3) + (l & 7)) * 272 + ((l >> 3) & 1) * 16;
#pragma unroll
        for (int ks = 0; ks < 8; ks++) {
            uint32_t ah[4][4];
#pragma unroll
            for (int mt = 0; mt < 4; mt++)
                LDM4(ah[mt], aBase + mt * 16 * 272 + ks * 32);
#pragma unroll
            for (int np = 0; np < 4; np++) {
                uint32_t bh[4];
                LDM4(bh, bBase + np * 16 * 272 + ks * 32);
#pragma unroll
                for (int mt = 0; mt < 4; mt++) {
                    MMA(acc[mt][np * 2 + 0], ah[mt], bh[0], bh[1]);
                    MMA(acc[mt][np * 2 + 1], ah[mt], bh[2], bh[3]);
                }
            }
        }
    }

    // exchange acc via smem: sgb[oc'][px], oc' 0-63 = gamma, 64-127 = beta (raw)
    __syncthreads();
    float* sgb = (float*)sm;  // 64KB (fits in 105536)
    int g = l >> 2, tg = l & 3;
#pragma unroll
    for (int nt = 0; nt < 8; nt++) {
        int c0 = ncol + nt * 8 + tg * 2;
#pragma unroll
        for (int mt = 0; mt < 4; mt++) {
            int pxl = mrow + mt * 16 + g;
            sgb[c0 * 128 + pxl]           = acc[mt][nt][0];
            sgb[(c0 + 1) * 128 + pxl]     = acc[mt][nt][1];
            sgb[c0 * 128 + pxl + 8]       = acc[mt][nt][2];
            sgb[(c0 + 1) * 128 + pxl + 8] = acc[mt][nt][3];
        }
    }
    __syncthreads();

    // fused final: out = lrelu( (dx-mu)*rstd*(1+gamma+bg) + beta+bb )
    for (int r = tid; r < 2048; r += 128) {
        int c = r >> 5, p4 = r & 31;
        float4 ga = *(float4*)&sgb[c * 128 + p4 * 4];
        float4 be = *(float4*)&sgb[(64 + c) * 128 + p4 * 4];
        float bgv = bg_[c], bbv = bb_[c];
        float m = g_stats[b * 64 + c], rs = g_stats[512 + b * 64 + c];
        size_t off = ((size_t)(b * 64 + c)) * HW + y * 256 + x0 + p4 * 4;
        float4 dx = *(const float4*)(g_dx + off);
        float4 o;
        float v;
        v = (dx.x - m) * rs * (1.f + ga.x + bgv) + be.x + bbv; o.x = v >= 0.f ? v : 0.2f * v;
        v = (dx.y - m) * rs * (1.f + ga.y + bgv) + be.y + bbv; o.y = v >= 0.f ? v : 0.2f * v;
        v = (dx.z - m) * rs * (1.f + ga.z + bgv) + be.z + bbv; o.z = v >= 0.f ? v : 0.2f * v;
        v = (dx.w - m) * rs * (1.f + ga.w + bgv) + be.w + bbv; o.w = v >= 0.f ? v : 0.2f * v;
        *(float4*)(out + off) = o;
    }
}

// ==================== instance-norm stats ====================
__global__ void k_stats() {
    int bc = blockIdx.x;
    int tid = threadIdx.x;
    const float4* p = (const float4*)(g_dx + (size_t)bc * HW);
    float s = 0.f, s2 = 0.f;
    for (int i = tid; i < HW / 4; i += 256) {
        float4 v = p[i];
        s  += v.x + v.y + v.z + v.w;
        s2 += v.x * v.x + v.y * v.y + v.z * v.z + v.w * v.w;
    }
    __shared__ float rs[256], rq[256];
    rs[tid] = s; rq[tid] = s2;
    __syncthreads();
    for (int o = 128; o > 0; o >>= 1) {
        if (tid < o) { rs[tid] += rs[tid + o]; rq[tid] += rq[tid + o]; }
        __syncthreads();
    }
    if (tid == 0) {
        float m = rs[0] * (1.f / HW);
        float var = rq[0] * (1.f / HW) - m * m;
        g_stats[bc] = m;
        g_stats[512 + bc] = rsqrtf(var + 1e-5f);
    }
}

// ==================== masked per-class mean pooling ====================
__global__ void k_pool(const int* __restrict__ seg, const float* __restrict__ bg,
                       const float* __restrict__ mask) {
    __shared__ float s_sum[64 * 36];
    __shared__ float s_cnt[36];
    int tid = threadIdx.x;
    for (int i = tid; i < 64 * 36; i += 256) s_sum[i] = 0.f;
    if (tid < 36) s_cnt[tid] = 0.f;
    __syncthreads();
    int b = blockIdx.y;
    int lane = tid & 31, cg = tid >> 5;
    int base = blockIdx.x * 4096;
    for (int p0 = 0; p0 < 4096; p0 += 32) {
        int p = base + p0 + lane;
        int s = seg[b * HW + p];
        bool q = (bg[b * HW + p] * (1.f - mask[b * HW + p])) > 0.f;
        if (q && cg == 0) atomicAdd(&s_cnt[s], 1.f);
        if (q) {
#pragma unroll
            for (int cc = 0; cc < 8; cc++) {
                int c = cg + cc * 8;
                float f = g_feat[((size_t)(b * 64 + c)) * HW + p];
                atomicAdd(&s_sum[c * 36 + s], f);
            }
        }
    }
    __syncthreads();
    for (int i = tid; i < 64 * 36; i += 256) {
        float v = s_sum[i];
        if (v != 0.f) atomicAdd(&g_sums[b * 2304 + i], v);
    }
    if (tid < 36 && s_cnt[tid] != 0.f) atomicAdd(&g_cnt[b * 36 + tid], s_cnt[tid]);
}

__global__ void k_codes() {
    int i = blockIdx.x * 256 + threadIdx.x;
    if (i >= BB * 35 * 64) return;
    int b = i / (35 * 64); int s = (i / 64) % 35; int f = i & 63;
    float cnt = g_cnt[b * 36 + s];
    bool keep = !(s >= 24 && s <= 33);
    float v = 0.f;
    if (cnt > 0.f && keep) v = g_sums[b * 2304 + f * 36 + s] / cnt;
    g_codes[i] = v;
}

__global__ void k_table(const float* __restrict__ w_sh) {
    int b = blockIdx.x / 9, k = blockIdx.x % 9;
    int o = threadIdx.x;  // 128
    __shared__ float swt[64][128];
    __shared__ float sc[64];
    for (int f = 0; f < 64; f++) swt[f][o] = w_sh[(o * 99 + f) * 9 + k];
    for (int s = 0; s < 35; s++) {
        __syncthreads();
        if (o < 64) sc[o] = g_codes[(b * 35 + s) * 64 + o];
        __syncthreads();
        float acc = w_sh[(o * 99 + 64 + s) * 9 + k];
#pragma unroll 8
        for (int f = 0; f < 64; f++)
            acc = fmaf(swt[f][o], sc[f], acc);
        g_table[((b * 9 + k) * 35 + s) * 128 + o] = acc;
    }
}

// ---------------- actv = relu(b_sh + table conv) -> NHWC fp16 ----------------
__global__ void k_actv(const int* __restrict__ seg, const float* __restrict__ bg,
                       const float* __restrict__ bsh) {
    __shared__ int ns[324];
    int b = blockIdx.z;
    int x0 = blockIdx.x * 16, y0 = blockIdx.y * 16;
    int tid = threadIdx.x;
    for (int i = tid; i < 324; i += 256) {
        int r = i / 18, c = i % 18;
        int gy = y0 - 1 + r, gx = x0 - 1 + c;
        int v = -1;
        if ((unsigned)gy < 256u && (unsigned)gx < 256u) {
            int p = gy * 256 + gx;
            if (bg[b * HW + p] > 0.f) v = seg[b * HW + p];
        }
        ns[i] = v;
    }
    __syncthreads();
    int oq = tid & 31, pg = tid >> 5;
    const float4* T4 = (const float4*)g_table + (size_t)b * 9 * 35 * 32;
    float4 bias = ((const float4*)bsh)[oq];
    for (int pp = pg * 32; pp < pg * 32 + 32; pp++) {
        int ly = pp >> 4, lx = pp & 15;
        float4 a = bias;
#pragma unroll
        for (int ky = 0; ky < 3; ky++)
#pragma unroll
            for (int kx = 0; kx < 3; kx++) {
                int idx = ns[(ly + ky) * 18 + lx + kx];
                if (idx >= 0) {
                    float4 t = T4[((ky * 3 + kx) * 35 + idx) * 32 + oq];
                    a.x += t.x; a.y += t.y; a.z += t.z; a.w += t.w;
                }
            }
        a.x = fmaxf(a.x, 0.f); a.y = fmaxf(a.y, 0.f);
        a.z = fmaxf(a.z, 0.f); a.w = fmaxf(a.w, 0.f);
        __half h0 = __float2half_rn(a.x), h1 = __float2half_rn(a.y);
        __half h2 = __float2half_rn(a.z), h3 = __float2half_rn(a.w);
        uint32_t w01 = (uint32_t)__half_as_ushort(h0) | ((uint32_t)__half_as_ushort(h1) << 16);
        uint32_t w23 = (uint32_t)__half_as_ushort(h2) | ((uint32_t)__half_as_ushort(h3) << 16);
        int gp = (y0 + ly) * 256 + x0 + lx;
        size_t base = (((size_t)b * HW + gp) << 7) + oq * 4;
        *(uint2*)(g_actv + base) = make_uint2(w01, w23);
    }
}

// ==================== host ====================
extern "C" void kernel_launch(void* const* d_in, const int* in_sizes, int n_in,
                              void* d_out, int out_size) {
    const float* featmap_in = (const float*)d_in[0];
    const int*   seg        = (const int*)  d_in[1];
    const float* bg         = (const float*)d_in[2];
    const float* mask       = (const float*)d_in[3];
    const float* w_conv     = (const float*)d_in[4];
    const float* b_conv     = (const float*)d_in[5];
    const float* w_c0       = (const float*)d_in[6];
    const float* b_c0       = (const float*)d_in[7];
    const float* w_sh       = (const float*)d_in[8];
    const float* b_sh       = (const float*)d_in[9];
    const float* w_g        = (const float*)d_in[10];
    const float* b_g        = (const float*)d_in[11];
    const float* w_b        = (const float*)d_in[12];
    const float* b_b        = (const float*)d_in[13];

    cudaFuncSetAttribute(k_conv1mma, cudaFuncAttributeMaxDynamicSharedMemorySize, SMEM_C1);
    cudaFuncSetAttribute(k_conv2mma, cudaFuncAttributeMaxDynamicSharedMemorySize, SMEM_C2);

    k_zero<<<72, 256>>>();
    k_wpack<<<576, 256>>>(w_conv, w_c0, w_g, w_b);
    k_split<<<dim3(1024, 8), 256>>>(featmap_in);

    // conv1 (lrelu -> g_feat) + conv_c0 (raw -> g_dx)
    k_conv1mma<<<dim3(2, 256, 8), 128, SMEM_C1>>>(b_conv, b_c0);

    k_stats<<<512, 256>>>();
    k_pool<<<dim3(16, 8), 256>>>(seg, bg, mask);
    k_codes<<<70, 256>>>();
    k_table<<<72, 128>>>(w_sh);
    k_actv<<<dim3(16, 16, 8), 256>>>(seg, bg, b_sh);

    // gamma/beta conv + fused instance-norm/SPADE/lrelu -> out
    k_conv2mma<<<dim3(2, 256, 8), 128, SMEM_C2>>>(b_g, b_b, (float*)d_out);
}